// round 15
// baseline (speedup 1.0000x reference)
#include <cuda_runtime.h>
#include <cuda_bf16.h>
#include <math.h>
#include <stdint.h>

// Problem constants
#define B_   2
#define S_   2048
#define HID_ 2048
#define NH_  16
#define NKV_ 8
#define HD_  256
#define F_   8192      // (NH + 2*NKV) * HD
#define M1_  4096      // B*S
#define EPS_ 1e-6f
#define SCALE_ 0.0625f // 256^-0.5
#define LOG2E_ 1.4426950408889634f
#define MSHIFT_ (6.0f * LOG2E_)   // fixed softmax shift (|S| <= 16, safe)

// Arch-specific feature gate: tcgen05 only exists on sm_103a/f passes.
#if defined(__CUDA_ARCH_FEAT_SM103_ALL) || defined(__CUDA_ARCH_SPECIFIC__) || defined(__CUDA_ARCH_FAMILY_SPECIFIC__)
#define TC_OK 1
#else
#define TC_OK 0
#endif

// Scratch (device globals, no allocation)
__device__ float g_qkv[(size_t)M1_ * F_];          // qkv projection (fp32)
__device__ __nv_bfloat16 g_h[(size_t)M1_ * F_];    // attn operands hi split
__device__ __nv_bfloat16 g_l[(size_t)M1_ * F_];    // attn operands lo split
// GEMM operand splits. Weights stored TRANSPOSED: [N][K] K-major.
__device__ __nv_bfloat16 g_hidh[(size_t)M1_ * HID_];
__device__ __nv_bfloat16 g_hidl[(size_t)M1_ * HID_];
__device__ __nv_bfloat16 g_wqh [(size_t)F_ * HID_];          // [F][HID]
__device__ __nv_bfloat16 g_wql [(size_t)F_ * HID_];
__device__ __nv_bfloat16 g_woh [(size_t)HID_ * (NH_*HD_)];   // [HID][NH*HD]
__device__ __nv_bfloat16 g_wol [(size_t)HID_ * (NH_*HD_)];
__device__ __nv_bfloat16 g_aoh [(size_t)M1_ * (NH_*HD_)];
__device__ __nv_bfloat16 g_aol [(size_t)M1_ * (NH_*HD_)];

// ---------------------------------------------------------------------------
// helpers (arch-neutral)
// ---------------------------------------------------------------------------
__device__ __forceinline__ uint32_t s2u(const void* p) {
    return (uint32_t)__cvta_generic_to_shared(p);
}
__device__ __forceinline__ float ex2f(float x) {
    float y; asm("ex2.approx.f32 %0, %1;" : "=f"(y) : "f"(x)); return y;
}
__device__ __forceinline__ uint32_t pack_bf16(float lo, float hi) {
    uint32_t r;
    asm("cvt.rn.bf16x2.f32 %0, %1, %2;" : "=r"(r) : "f"(hi), "f"(lo));
    return r;
}
__device__ __forceinline__ float bf_round(float x) {
    return __bfloat162float(__float2bfloat16(x));
}
__device__ __forceinline__ void cp16(uint32_t s, const void* g) {
    asm volatile("cp.async.cg.shared.global [%0], [%1], 16;" :: "r"(s), "l"(g));
}
#define CP_COMMIT asm volatile("cp.async.commit_group;")
#define CP_WAIT(n) asm volatile("cp.async.wait_group %0;" :: "n"(n))

#define MMA_BF16(c, a, b) \
    asm volatile("mma.sync.aligned.m16n8k16.row.col.f32.bf16.bf16.f32 " \
        "{%0,%1,%2,%3}, {%4,%5,%6,%7}, {%8,%9}, {%0,%1,%2,%3};" \
        : "+f"((c)[0]), "+f"((c)[1]), "+f"((c)[2]), "+f"((c)[3]) \
        : "r"((a)[0]), "r"((a)[1]), "r"((a)[2]), "r"((a)[3]), \
          "r"((b)[0]), "r"((b)[1]))

#define LDSM_X4(r0, r1, r2, r3, addr) \
    asm volatile("ldmatrix.sync.aligned.m8n8.x4.shared.b16 {%0,%1,%2,%3}, [%4];" \
        : "=r"(r0), "=r"(r1), "=r"(r2), "=r"(r3) : "r"(addr))

#define LDSM_X2T(r0, r1, addr) \
    asm volatile("ldmatrix.sync.aligned.m8n8.x2.trans.shared.b16 {%0,%1}, [%2];" \
        : "=r"(r0), "=r"(r1) : "r"(addr))

// ---------------------------------------------------------------------------
// Generic fp32 -> bf16 hi/lo split (memory-bound)
// ---------------------------------------------------------------------------
__global__ __launch_bounds__(256) void split_f32_kernel(
    const float* __restrict__ in, __nv_bfloat16* __restrict__ hi,
    __nv_bfloat16* __restrict__ lo, int n4)
{
    int i = blockIdx.x * 256 + threadIdx.x;
    if (i >= n4) return;
    float4 v = ((const float4*)in)[i];
    float h0 = bf_round(v.x), h1 = bf_round(v.y);
    float h2 = bf_round(v.z), h3 = bf_round(v.w);
    uint2 hp, lp;
    hp.x = pack_bf16(h0, h1);
    hp.y = pack_bf16(h2, h3);
    lp.x = pack_bf16(v.x - h0, v.y - h1);
    lp.y = pack_bf16(v.z - h2, v.w - h3);
    ((uint2*)hi)[i] = hp;
    ((uint2*)lo)[i] = lp;
}

// ---------------------------------------------------------------------------
// Transpose + split: in [R][C] fp32 -> hi/lo [C][R] bf16. 32x32 smem tiles.
// ---------------------------------------------------------------------------
__global__ __launch_bounds__(256) void transpose_split_kernel(
    const float* __restrict__ in, __nv_bfloat16* __restrict__ hi,
    __nv_bfloat16* __restrict__ lo, int R, int C)
{
    __shared__ float tile[32][33];
    const int tx = threadIdx.x & 31;
    const int ty = threadIdx.x >> 5;
    const int bx = blockIdx.x * 32;  // C offset
    const int by = blockIdx.y * 32;  // R offset

    #pragma unroll
    for (int i = 0; i < 4; i++)
        tile[ty + i * 8][tx] = in[(size_t)(by + ty + i * 8) * C + bx + tx];
    __syncthreads();

    #pragma unroll
    for (int i = 0; i < 4; i++) {
        int r = by + tx;
        int c = bx + ty + i * 8;
        float v = tile[tx][ty + i * 8];
        float h = bf_round(v);
        hi[(size_t)c * R + r] = __float2bfloat16(h);
        lo[(size_t)c * R + r] = __float2bfloat16(v - h);
    }
}

// ---------------------------------------------------------------------------
// GEMM: C[M,N] = A[M,K] @ B'[N,K]^T, fp32 out. CTA tile 128(M) x 256(N).
// TC path: tcgen05 SS-mode, BK=64, SW128, depth-2 with shifted buffer-reuse
// wait (wait MMA(c-1) at iter c — one iteration old, free) so MMA issue and
// loads overlap. Fallback: mma.sync bf16x3 for the non-arch-specific pass.
// ---------------------------------------------------------------------------
#define TCG_PART   16384                 // 128 rows x 128B
#define TCG_STAGE  (6 * TCG_PART)        // Ah Al B0h B0l B1h B1l = 96KB
#define TCG_SMEM   (1024 + 2 * TCG_STAGE)

#if TC_OK
__device__ __forceinline__ void tc_mbar_wait(uint32_t mbar, uint32_t parity) {
    asm volatile(
        "{\n\t.reg .pred P;\n\t"
        "W%=:\n\t"
        "mbarrier.try_wait.parity.shared.b64 P, [%0], %1, 0x989680;\n\t"
        "@P bra D%=;\n\t"
        "bra W%=;\n\t"
        "D%=:\n\t}"
        :: "r"(mbar), "r"(parity) : "memory");
}
__device__ __forceinline__ uint64_t sw128_desc(uint32_t addr) {
    return ((uint64_t)2 << 61) | ((uint64_t)1 << 46)
         | ((uint64_t)64 << 32) | ((uint64_t)1 << 16)
         | ((addr >> 4) & 0x3FFF);
}
__device__ __forceinline__ void tc_mma_f16_ss(
    uint32_t d, uint64_t a, uint64_t b, uint32_t idesc, uint32_t en) {
    asm volatile(
        "{\n\t.reg .pred p;\n\tsetp.ne.u32 p, %4, 0;\n\t"
        "tcgen05.mma.cta_group::1.kind::f16 [%0], %1, %2, %3, {%5,%5,%5,%5}, p;\n\t}"
        :: "r"(d), "l"(a), "l"(b), "r"(idesc), "r"(en), "r"(0u) : "memory");
}
// idesc kind::f16: fp32 accum (bit4), bf16 a/b (bits7,10), N=128, M=128
#define TC_IDESC ((1u << 4) | (1u << 7) | (1u << 10) | (16u << 17) | (8u << 24))
#define TC_LD_X32(r, addr) \
    asm volatile("tcgen05.ld.sync.aligned.32x32b.x32.b32 " \
        "{%0, %1, %2, %3, %4, %5, %6, %7, %8, %9, %10, %11, %12, %13, %14, %15, " \
        " %16, %17, %18, %19, %20, %21, %22, %23, %24, %25, %26, %27, %28, %29, %30, %31}, [%32];" \
        : "=r"((r)[0]), "=r"((r)[1]), "=r"((r)[2]), "=r"((r)[3]), \
          "=r"((r)[4]), "=r"((r)[5]), "=r"((r)[6]), "=r"((r)[7]), \
          "=r"((r)[8]), "=r"((r)[9]), "=r"((r)[10]), "=r"((r)[11]), \
          "=r"((r)[12]), "=r"((r)[13]), "=r"((r)[14]), "=r"((r)[15]), \
          "=r"((r)[16]), "=r"((r)[17]), "=r"((r)[18]), "=r"((r)[19]), \
          "=r"((r)[20]), "=r"((r)[21]), "=r"((r)[22]), "=r"((r)[23]), \
          "=r"((r)[24]), "=r"((r)[25]), "=r"((r)[26]), "=r"((r)[27]), \
          "=r"((r)[28]), "=r"((r)[29]), "=r"((r)[30]), "=r"((r)[31]) \
        : "r"(addr))
#endif

__global__ __launch_bounds__(256, 1) void tc_gemm_kernel(
    const __nv_bfloat16* __restrict__ Ah, const __nv_bfloat16* __restrict__ Al,
    const __nv_bfloat16* __restrict__ Bh, const __nv_bfloat16* __restrict__ Bl,
    float* __restrict__ C, int M, int N, int K)
{
    extern __shared__ char ts[];
#if TC_OK
    // ======================= tcgen05 path (sm_103a) =======================
    const uint32_t base = s2u(ts);
    const int tid  = threadIdx.x;
    const int wid  = tid >> 5;
    const int lane = tid & 31;
    const int brow = blockIdx.y * 128;
    const int bcol = blockIdx.x * 256;
    const int nch  = K >> 6;

    const uint32_t TMEM_PTR = base;
    const uint32_t MBAR     = base + 8;      // two 8B mbarriers
    const uint32_t STG0     = base + 1024;

    const __nv_bfloat16* srcs[6];
    srcs[0] = Ah + (size_t)brow * K;
    srcs[1] = Al + (size_t)brow * K;
    srcs[2] = Bh + (size_t)bcol * K;
    srcs[3] = Bl + (size_t)bcol * K;
    srcs[4] = Bh + (size_t)(bcol + 128) * K;
    srcs[5] = Bl + (size_t)(bcol + 128) * K;

    auto load_chunk = [&](int c) {
        uint32_t st = STG0 + (uint32_t)(c & 1) * TCG_STAGE;
        int k0 = c * 64;
        #pragma unroll
        for (int p = 0; p < 6; p++) {
            #pragma unroll
            for (int i = 0; i < 4; i++) {
                int idx = tid + i * 256;
                int row = idx >> 3;
                int c16 = idx & 7;
                uint32_t dst = st + p * TCG_PART + row * 128
                             + (uint32_t)((c16 ^ (row & 7)) << 4);
                cp16(dst, srcs[p] + (size_t)row * K + k0 + c16 * 8);
            }
        }
    };

    // prologue: two chunks in flight
    load_chunk(0); CP_COMMIT;
    load_chunk(1); CP_COMMIT;

    if (wid == 0) {
        asm volatile("tcgen05.alloc.cta_group::1.sync.aligned.shared::cta.b32 [%0], %1;"
                     :: "r"(TMEM_PTR), "r"(256) : "memory");
    }
    if (tid == 0) {
        asm volatile("mbarrier.init.shared.b64 [%0], %1;" :: "r"(MBAR), "r"(1) : "memory");
        asm volatile("mbarrier.init.shared.b64 [%0], %1;" :: "r"(MBAR + 8), "r"(1) : "memory");
    }
    __syncthreads();
    uint32_t tbase;
    asm volatile("ld.shared.b32 %0, [%1];" : "=r"(tbase) : "r"(TMEM_PTR));
    const uint32_t d0 = tbase, d1 = tbase + 128;

    for (int c = 0; c < nch; c++) {
        // (a) shifted buffer-reuse: load(c+1) overwrites MMA(c-1)'s buffer;
        //     that MMA was committed a full iteration ago -> wait is ~free.
        if (c >= 1 && c + 1 < nch) {
            tc_mbar_wait(MBAR + (uint32_t)((c - 1) & 1) * 8,
                         (uint32_t)(((c - 1) >> 1) & 1));
            load_chunk(c + 1);
            CP_COMMIT;
        }

        // (b) ensure load(c) landed (the newer group may stay pending)
        if (c + 1 < nch) { CP_WAIT(1); } else { CP_WAIT(0); }
        __syncthreads();

        // (c) issue the chunk's MMAs
        if (tid == 0) {
            asm volatile("fence.proxy.async;" ::: "memory");
            uint32_t st = STG0 + (uint32_t)(c & 1) * TCG_STAGE;
            uint64_t aH  = sw128_desc(st);
            uint64_t aL  = sw128_desc(st + TCG_PART);
            uint64_t b0h = sw128_desc(st + 2 * TCG_PART);
            uint64_t b0l = sw128_desc(st + 3 * TCG_PART);
            uint64_t b1h = sw128_desc(st + 4 * TCG_PART);
            uint64_t b1l = sw128_desc(st + 5 * TCG_PART);
            #pragma unroll
            for (int ks = 0; ks < 4; ks++) {
                uint32_t en0 = (c == 0 && ks == 0) ? 0u : 1u;
                uint64_t o = (uint64_t)(ks * 2);
                tc_mma_f16_ss(d0, aH + o, b0h + o, TC_IDESC, en0);
                tc_mma_f16_ss(d0, aH + o, b0l + o, TC_IDESC, 1u);
                tc_mma_f16_ss(d0, aL + o, b0h + o, TC_IDESC, 1u);
                tc_mma_f16_ss(d1, aH + o, b1h + o, TC_IDESC, en0);
                tc_mma_f16_ss(d1, aH + o, b1l + o, TC_IDESC, 1u);
                tc_mma_f16_ss(d1, aL + o, b1h + o, TC_IDESC, 1u);
            }
            asm volatile(
                "tcgen05.commit.cta_group::1.mbarrier::arrive::one.shared::cluster.b64 [%0];"
                :: "r"(MBAR + (uint32_t)(c & 1) * 8) : "memory");
        }
    }

    // final wait: last chunk's commit covers all prior MMAs
    tc_mbar_wait(MBAR + (uint32_t)((nch - 1) & 1) * 8,
                 (uint32_t)(((nch - 1) >> 1) & 1));
    asm volatile("tcgen05.fence::after_thread_sync;" ::: "memory");

    // epilogue: warp w reads rows (w&3)*32, cols (w>>2)*64, both D tiles
    {
        const int row = brow + (wid & 3) * 32 + lane;
        #pragma unroll
        for (int t = 0; t < 2; t++) {
            #pragma unroll
            for (int hlf = 0; hlf < 2; hlf++) {
                uint32_t col = (uint32_t)(t * 128 + (wid >> 2) * 64 + hlf * 32);
                uint32_t r[32];
                TC_LD_X32(r, tbase + col);
                asm volatile("tcgen05.wait::ld.sync.aligned;" ::: "memory");
                float* cp = C + (size_t)row * N + bcol + col;
                #pragma unroll
                for (int j = 0; j < 8; j++) {
                    float4 v = make_float4(__uint_as_float(r[4 * j]),
                                           __uint_as_float(r[4 * j + 1]),
                                           __uint_as_float(r[4 * j + 2]),
                                           __uint_as_float(r[4 * j + 3]));
                    *(float4*)(cp + 4 * j) = v;
                }
            }
        }
    }

    __syncthreads();
    if (wid == 0) {
        asm volatile("tcgen05.relinquish_alloc_permit.cta_group::1.sync.aligned;");
        asm volatile("tcgen05.dealloc.cta_group::1.sync.aligned.b32 %0, %1;"
                     :: "r"(tbase), "r"(256));
    }
#else
    // =================== mma.sync fallback (compute_103) ===================
    const int tid  = threadIdx.x;
    const int lane = tid & 31;
    const int wid  = tid >> 5;
    const int brow = blockIdx.y * 128;
    const int wm   = (wid >> 2) * 64;
    const int wn   = (wid & 3) * 32;
    const uint32_t gs_u = s2u(ts);
    const int nchunks = K / 32;

    const int fr  = (lane & 7) + ((lane >> 4) & 1) * 8;
    const int fc8 = ((lane >> 3) & 1) << 3;

    #pragma unroll 1
    for (int half = 0; half < 2; half++) {
        const int bcol = blockIdx.x * 256 + half * 128;

        auto load_stage = [&](int chunk, int s) {
            uint32_t st = gs_u + (uint32_t)s * 40960;
            int k0 = chunk * 32;
            #pragma unroll
            for (int t = 0; t < 2; t++) {
                int idx = tid + t * 256;
                int r = idx >> 2, c4 = idx & 3;
                size_t ga = (size_t)(brow + r) * K + k0 + c4 * 8;
                size_t gb = (size_t)(bcol + r) * K + k0 + c4 * 8;
                uint32_t off = (uint32_t)(r * 80 + c4 * 16);
                cp16(st + off,             Ah + ga);
                cp16(st + 10240 + off,     Al + ga);
                cp16(st + 2 * 10240 + off, Bh + gb);
                cp16(st + 3 * 10240 + off, Bl + gb);
            }
        };

        float acc[4][4][4];
        #pragma unroll
        for (int i = 0; i < 4; i++)
            #pragma unroll
            for (int j = 0; j < 4; j++)
                #pragma unroll
                for (int r = 0; r < 4; r++) acc[i][j][r] = 0.f;

        load_stage(0, 0);
        CP_COMMIT;

        for (int c = 0; c < nchunks; c++) {
            if (c + 1 < nchunks) {
                load_stage(c + 1, (c + 1) & 1);
                CP_COMMIT;
                CP_WAIT(1);
            } else {
                CP_WAIT(0);
            }
            __syncthreads();

            uint32_t sa = gs_u + (uint32_t)(c & 1) * 40960;
            uint32_t sb = sa + 2 * 10240;

            #pragma unroll
            for (int ks = 0; ks < 2; ks++) {
                const int kb = ks * 16;
                uint32_t bhf[4][2], blf[4][2];
                #pragma unroll
                for (int jj = 0; jj < 2; jj++) {
                    uint32_t ad = sb + (wn + jj * 16 + fr) * 80 + (kb + fc8) * 2;
                    uint32_t tq[4], uq[4];
                    LDSM_X4(tq[0], tq[1], tq[2], tq[3], ad);
                    LDSM_X4(uq[0], uq[1], uq[2], uq[3], ad + 10240);
                    bhf[2 * jj][0] = tq[0]; bhf[2 * jj][1] = tq[1];
                    bhf[2 * jj + 1][0] = tq[2]; bhf[2 * jj + 1][1] = tq[3];
                    blf[2 * jj][0] = uq[0]; blf[2 * jj][1] = uq[1];
                    blf[2 * jj + 1][0] = uq[2]; blf[2 * jj + 1][1] = uq[3];
                }
                #pragma unroll
                for (int i = 0; i < 4; i++) {
                    uint32_t ahf[4], alf[4];
                    uint32_t ad = sa + (wm + i * 16 + (lane & 15)) * 80
                                + (kb + ((lane >> 4) << 3)) * 2;
                    LDSM_X4(ahf[0], ahf[1], ahf[2], ahf[3], ad);
                    LDSM_X4(alf[0], alf[1], alf[2], alf[3], ad + 10240);
                    #pragma unroll
                    for (int j = 0; j < 4; j++) {
                        MMA_BF16(acc[i][j], ahf, bhf[j]);
                        MMA_BF16(acc[i][j], ahf, blf[j]);
                        MMA_BF16(acc[i][j], alf, bhf[j]);
                    }
                }
            }
            __syncthreads();
        }

        const int grp = lane >> 2;
        const int tig = lane & 3;
        #pragma unroll
        for (int i = 0; i < 4; i++) {
            #pragma unroll
            for (int j = 0; j < 4; j++) {
                int row = brow + wm + i * 16 + grp;
                int col = bcol + wn + j * 8 + tig * 2;
                float* c0 = &C[(size_t)row * N + col];
                c0[0] = acc[i][j][0];
                c0[1] = acc[i][j][1];
                float* c1 = c0 + (size_t)8 * N;
                c1[0] = acc[i][j][2];
                c1[1] = acc[i][j][3];
            }
        }
        __syncthreads();
    }
#endif
}

// ---------------------------------------------------------------------------
// RMSNorm+RoPE split kernel (unchanged)
// ---------------------------------------------------------------------------
__global__ __launch_bounds__(256) void split_kernel(
    const float* __restrict__ qkv, const float* __restrict__ cosb,
    const float* __restrict__ sinb, const float* __restrict__ qw,
    const float* __restrict__ kw, __nv_bfloat16* __restrict__ gh,
    __nv_bfloat16* __restrict__ gl)
{
    const int blk = blockIdx.x;
    const int h32 = blk & 31;
    const int bs  = blk >> 5;
    const int tid = threadIdx.x;

    const size_t base = (size_t)bs * F_ + h32 * HD_;
    float x = qkv[base + tid];
    float val;

    if (h32 < NH_ + NKV_) {
        float ss = x * x;
        #pragma unroll
        for (int m = 16; m; m >>= 1) ss += __shfl_xor_sync(~0u, ss, m);
        __shared__ float warpsum[8];
        __shared__ float xn_s[HD_];
        if ((tid & 31) == 0) warpsum[tid >> 5] = ss;
        __syncthreads();
        float tot = warpsum[0] + warpsum[1] + warpsum[2] + warpsum[3]
                  + warpsum[4] + warpsum[5] + warpsum[6] + warpsum[7];
        float inv = rsqrtf(tot * (1.0f / HD_) + EPS_);
        const float* w = (h32 < NH_) ? qw : kw;
        float xn = x * inv * (1.0f + w[tid]);
        xn_s[tid] = xn;
        __syncthreads();
        float rot = (tid < HD_ / 2) ? -xn_s[tid + HD_ / 2] : xn_s[tid - HD_ / 2];
        float c = cosb[(size_t)bs * HD_ + tid];
        float s = sinb[(size_t)bs * HD_ + tid];
        val = xn * c + rot * s;
        if (h32 < NH_) val *= SCALE_;
    } else {
        val = x;
    }

    __nv_bfloat16 hi = __float2bfloat16(val);
    gh[base + tid] = hi;
    gl[base + tid] = __float2bfloat16(val - __bfloat162float(hi));
}

// ---------------------------------------------------------------------------
// MMA flash attention (R13: fixed-max softmax; x2.trans V; bf16 epilogue)
// ---------------------------------------------------------------------------
#define QSTR 264
#define TK 32
#define NT_ (S_ / TK)
#define FATTN_SMEM ((128 * QSTR * 2 + TK * QSTR * 4) * 2)

__global__ __launch_bounds__(256, 1) void fattn_kernel(
    const __nv_bfloat16* __restrict__ gh, const __nv_bfloat16* __restrict__ gl,
    __nv_bfloat16* __restrict__ aoh, __nv_bfloat16* __restrict__ aol)
{
    extern __shared__ __nv_bfloat16 sm[];
    __nv_bfloat16* QH = sm;
    __nv_bfloat16* QL = QH + 128 * QSTR;
    __nv_bfloat16* KH = QL + 128 * QSTR;
    __nv_bfloat16* KL = KH + TK * QSTR;
    __nv_bfloat16* VH = KL + TK * QSTR;
    __nv_bfloat16* VL = VH + TK * QSTR;

    const int tid = threadIdx.x;
    const int w = tid >> 5;
    const int l = tid & 31;

    const int qt = blockIdx.x & 15;
    const int h  = (blockIdx.x >> 4) & 15;
    const int b  = blockIdx.x >> 8;
    const int kvh = h >> 1;
    const int q0 = qt * 128;

    const size_t koff = (size_t)NH_ * HD_ + kvh * HD_;
    const size_t voff = (size_t)(NH_ + NKV_) * HD_ + kvh * HD_;

    for (int i = tid; i < 128 * 32; i += 256) {
        int r = i >> 5, c = i & 31;
        size_t src = ((size_t)(b * S_ + q0 + r)) * F_ + h * HD_ + c * 8;
        int dst = r * QSTR + c * 8;
        *(uint4*)(QH + dst) = *(const uint4*)(gh + src);
        *(uint4*)(QL + dst) = *(const uint4*)(gl + src);
    }
    __syncthreads();

    float o[32][4];
    #pragma unroll
    for (int nt = 0; nt < 32; nt++)
        #pragma unroll
        for (int j = 0; j < 4; j++) o[nt][j] = 0.f;

    float l_lo = 0.f, l_hi = 0.f;

    const uint32_t qh_b = s2u(QH), ql_b = s2u(QL);
    const uint32_t kh_b = s2u(KH), kl_b = s2u(KL);
    const uint32_t vh_b = s2u(VH), vl_b = s2u(VL);

    const int qrow  = 16 * w + (l & 15);
    const int qcol8 = (l >> 4) << 3;
    const int krow  = (l & 7) + ((l >> 4) & 1) * 8;
    const int kcol8 = ((l >> 3) & 1) << 3;
    const int vrow  = l & 15;

    for (int kt = 0; kt < NT_; kt++) {
        __syncthreads();
        for (int i = tid; i < TK * 32; i += 256) {
            int r = i >> 5, c = i & 31;
            size_t base = ((size_t)(b * S_ + kt * TK + r)) * F_;
            int dst = r * QSTR + c * 8;
            *(uint4*)(KH + dst) = *(const uint4*)(gh + base + koff + c * 8);
            *(uint4*)(KL + dst) = *(const uint4*)(gl + base + koff + c * 8);
            *(uint4*)(VH + dst) = *(const uint4*)(gh + base + voff + c * 8);
            *(uint4*)(VL + dst) = *(const uint4*)(gl + base + voff + c * 8);
        }
        __syncthreads();

        float sA[4][4];
        #pragma unroll
        for (int nt = 0; nt < 4; nt++)
            #pragma unroll
            for (int j = 0; j < 4; j++) sA[nt][j] = 0.f;

        #pragma unroll
        for (int ks = 0; ks < 16; ks++) {
            uint32_t ah[4], al[4];
            uint32_t qoff = (uint32_t)(qrow * QSTR + ks * 16 + qcol8) * 2;
            LDSM_X4(ah[0], ah[1], ah[2], ah[3], qh_b + qoff);
            LDSM_X4(al[0], al[1], al[2], al[3], ql_b + qoff);
            #pragma unroll
            for (int ntp = 0; ntp < 2; ntp++) {
                uint32_t bh[4], bl[4];
                uint32_t kofs = (uint32_t)((16 * ntp + krow) * QSTR + ks * 16 + kcol8) * 2;
                LDSM_X4(bh[0], bh[1], bh[2], bh[3], kh_b + kofs);
                LDSM_X4(bl[0], bl[1], bl[2], bl[3], kl_b + kofs);
                MMA_BF16(sA[2 * ntp],     ah, bh);
                MMA_BF16(sA[2 * ntp],     ah, bl);
                MMA_BF16(sA[2 * ntp],     al, bh);
                MMA_BF16(sA[2 * ntp + 1], ah, bh + 2);
                MMA_BF16(sA[2 * ntp + 1], ah, bl + 2);
                MMA_BF16(sA[2 * ntp + 1], al, bh + 2);
            }
        }

        // fixed-max softmax: P = exp(S - 6)
        #pragma unroll
        for (int nt = 0; nt < 4; nt++) {
            sA[nt][0] = ex2f(fmaf(sA[nt][0], LOG2E_, -MSHIFT_));
            sA[nt][1] = ex2f(fmaf(sA[nt][1], LOG2E_, -MSHIFT_));
            sA[nt][2] = ex2f(fmaf(sA[nt][2], LOG2E_, -MSHIFT_));
            sA[nt][3] = ex2f(fmaf(sA[nt][3], LOG2E_, -MSHIFT_));
            l_lo += sA[nt][0] + sA[nt][1];
            l_hi += sA[nt][2] + sA[nt][3];
        }

        uint32_t aPh[2][4], aPl[2][4];
        #pragma unroll
        for (int ksp = 0; ksp < 2; ksp++) {
            #pragma unroll
            for (int q = 0; q < 4; q++) {
                int nt = 2 * ksp + (q >> 1);
                int j0 = (q & 1) * 2;
                float p0 = sA[nt][j0], p1 = sA[nt][j0 + 1];
                float h0 = bf_round(p0), h1 = bf_round(p1);
                aPh[ksp][q] = pack_bf16(h0, h1);
                aPl[ksp][q] = pack_bf16(p0 - h0, p1 - h1);
            }
        }

        #pragma unroll
        for (int ksp = 0; ksp < 2; ksp++) {
            #pragma unroll
            for (int nt = 0; nt < 32; nt++) {
                uint32_t vofs = (uint32_t)((16 * ksp + vrow) * QSTR + nt * 8) * 2;
                uint32_t bv[2], bw[2];
                LDSM_X2T(bv[0], bv[1], vh_b + vofs);
                LDSM_X2T(bw[0], bw[1], vl_b + vofs);
                MMA_BF16(o[nt], aPh[ksp], bv);
                MMA_BF16(o[nt], aPh[ksp], bw);
                MMA_BF16(o[nt], aPl[ksp], bv);
            }
        }
    }

    l_lo += __shfl_xor_sync(~0u, l_lo, 1);
    l_lo += __shfl_xor_sync(~0u, l_lo, 2);
    l_hi += __shfl_xor_sync(~0u, l_hi, 1);
    l_hi += __shfl_xor_sync(~0u, l_hi, 2);

    float inv_lo = 1.0f / l_lo;
    float inv_hi = 1.0f / l_hi;
    const int row_lo = q0 + 16 * w + (l >> 2);
    const int col0 = h * HD_ + 2 * (l & 3);
    #pragma unroll
    for (int nt = 0; nt < 32; nt++) {
        float v0 = o[nt][0] * inv_lo, v1 = o[nt][1] * inv_lo;
        float v2 = o[nt][2] * inv_hi, v3 = o[nt][3] * inv_hi;
        float h0 = bf_round(v0), h1 = bf_round(v1);
        float h2 = bf_round(v2), h3 = bf_round(v3);
        size_t i0 = (size_t)(b * S_ + row_lo)     * (NH_ * HD_) + col0 + nt * 8;
        size_t i1 = (size_t)(b * S_ + row_lo + 8) * (NH_ * HD_) + col0 + nt * 8;
        *(uint32_t*)(aoh + i0) = pack_bf16(h0, h1);
        *(uint32_t*)(aol + i0) = pack_bf16(v0 - h0, v1 - h1);
        *(uint32_t*)(aoh + i1) = pack_bf16(h2, h3);
        *(uint32_t*)(aol + i1) = pack_bf16(v2 - h2, v3 - h3);
    }
}

// ---------------------------------------------------------------------------
// Launch
// ---------------------------------------------------------------------------
extern "C" void kernel_launch(void* const* d_in, const int* in_sizes, int n_in,
                              void* d_out, int out_size)
{
    const float* hidden = (const float*)d_in[0];
    const float* cosb   = (const float*)d_in[1];
    const float* sinb   = (const float*)d_in[2];
    const float* w_qkv  = (const float*)d_in[3];
    const float* w_o    = (const float*)d_in[4];
    const float* q_w    = (const float*)d_in[5];
    const float* k_w    = (const float*)d_in[6];
    float* out = (float*)d_out;

    float* qkv; cudaGetSymbolAddress((void**)&qkv, g_qkv);
    __nv_bfloat16 *gh, *gl, *hidh, *hidl, *wqh, *wql, *woh, *wol, *aoh, *aol;
    cudaGetSymbolAddress((void**)&gh,   g_h);
    cudaGetSymbolAddress((void**)&gl,   g_l);
    cudaGetSymbolAddress((void**)&hidh, g_hidh);
    cudaGetSymbolAddress((void**)&hidl, g_hidl);
    cudaGetSymbolAddress((void**)&wqh,  g_wqh);
    cudaGetSymbolAddress((void**)&wql,  g_wql);
    cudaGetSymbolAddress((void**)&woh,  g_woh);
    cudaGetSymbolAddress((void**)&wol,  g_wol);
    cudaGetSymbolAddress((void**)&aoh,  g_aoh);
    cudaGetSymbolAddress((void**)&aol,  g_aol);

    cudaFuncSetAttribute(fattn_kernel, cudaFuncAttributeMaxDynamicSharedMemorySize,
                         FATTN_SMEM);
    cudaFuncSetAttribute(tc_gemm_kernel, cudaFuncAttributeMaxDynamicSharedMemorySize,
                         TCG_SMEM);

    // 0) Split hidden; transpose+split weights to [N][K]
    {
        int n4 = M1_ * HID_ / 4;
        split_f32_kernel<<<(n4 + 255) / 256, 256>>>(hidden, hidh, hidl, n4);
        dim3 gq(F_ / 32, HID_ / 32);
        transpose_split_kernel<<<gq, 256>>>(w_qkv, wqh, wql, HID_, F_);
        dim3 go(HID_ / 32, (NH_ * HD_) / 32);
        transpose_split_kernel<<<go, 256>>>(w_o, woh, wol, NH_ * HD_, HID_);
    }

    // 1) QKV projection: [4096,2048] @ [2048,8192]
    {
        dim3 grid(F_ / 256, M1_ / 128);
        tc_gemm_kernel<<<grid, 256, TCG_SMEM>>>(hidh, hidl, wqh, wql,
                                                qkv, M1_, F_, HID_);
    }

    // 2) RMSNorm + RoPE + bf16 hi/lo split for attention
    split_kernel<<<M1_ * 32, 256>>>(qkv, cosb, sinb, q_w, k_w, gh, gl);

    // 3) Flash attention (tensor cores) -> writes bf16 hi/lo O-proj input
    fattn_kernel<<<B_ * NH_ * (S_ / 128), 256, FATTN_SMEM>>>(gh, gl, aoh, aol);

    // 4) Output projection: [4096,4096] @ [4096,2048]
    {
        dim3 grid(HID_ / 256, M1_ / 128);
        tc_gemm_kernel<<<grid, 256, TCG_SMEM>>>(aoh, aol, woh, wol,
                                                out, M1_, HID_, NH_ * HD_);
    }
}

// round 16
// speedup vs baseline: 1.0074x; 1.0074x over previous
#include <cuda_runtime.h>
#include <cuda_bf16.h>
#include <math.h>
#include <stdint.h>

// Problem constants
#define B_   2
#define S_   2048
#define HID_ 2048
#define NH_  16
#define NKV_ 8
#define HD_  256
#define F_   8192      // (NH + 2*NKV) * HD
#define M1_  4096      // B*S
#define EPS_ 1e-6f
#define SCALE_ 0.0625f // 256^-0.5
#define LOG2E_ 1.4426950408889634f
#define MSHIFT_ (6.0f * LOG2E_)   // fixed softmax shift (|S| <= 16, safe)

// Arch-specific feature gate: tcgen05 only exists on sm_103a/f passes.
#if defined(__CUDA_ARCH_FEAT_SM103_ALL) || defined(__CUDA_ARCH_SPECIFIC__) || defined(__CUDA_ARCH_FAMILY_SPECIFIC__)
#define TC_OK 1
#else
#define TC_OK 0
#endif

// Scratch (device globals, no allocation)
__device__ float g_qkv[(size_t)M1_ * F_];          // qkv projection (fp32)
__device__ __nv_bfloat16 g_h[(size_t)M1_ * F_];    // attn operands hi split
__device__ __nv_bfloat16 g_l[(size_t)M1_ * F_];    // attn operands lo split
// GEMM operand splits. Weights stored TRANSPOSED: [N][K] K-major.
__device__ __nv_bfloat16 g_hidh[(size_t)M1_ * HID_];
__device__ __nv_bfloat16 g_hidl[(size_t)M1_ * HID_];
__device__ __nv_bfloat16 g_wqh [(size_t)F_ * HID_];          // [F][HID]
__device__ __nv_bfloat16 g_wql [(size_t)F_ * HID_];
__device__ __nv_bfloat16 g_woh [(size_t)HID_ * (NH_*HD_)];   // [HID][NH*HD]
__device__ __nv_bfloat16 g_wol [(size_t)HID_ * (NH_*HD_)];
__device__ __nv_bfloat16 g_aoh [(size_t)M1_ * (NH_*HD_)];
__device__ __nv_bfloat16 g_aol [(size_t)M1_ * (NH_*HD_)];

// ---------------------------------------------------------------------------
// helpers (arch-neutral)
// ---------------------------------------------------------------------------
__device__ __forceinline__ uint32_t s2u(const void* p) {
    return (uint32_t)__cvta_generic_to_shared(p);
}
__device__ __forceinline__ float ex2f(float x) {
    float y; asm("ex2.approx.f32 %0, %1;" : "=f"(y) : "f"(x)); return y;
}
__device__ __forceinline__ uint32_t pack_bf16(float lo, float hi) {
    uint32_t r;
    asm("cvt.rn.bf16x2.f32 %0, %1, %2;" : "=r"(r) : "f"(hi), "f"(lo));
    return r;
}
__device__ __forceinline__ float bf_round(float x) {
    return __bfloat162float(__float2bfloat16(x));
}
__device__ __forceinline__ void cp16(uint32_t s, const void* g) {
    asm volatile("cp.async.cg.shared.global [%0], [%1], 16;" :: "r"(s), "l"(g));
}
#define CP_COMMIT asm volatile("cp.async.commit_group;")
#define CP_WAIT(n) asm volatile("cp.async.wait_group %0;" :: "n"(n))

#define MMA_BF16(c, a, b) \
    asm volatile("mma.sync.aligned.m16n8k16.row.col.f32.bf16.bf16.f32 " \
        "{%0,%1,%2,%3}, {%4,%5,%6,%7}, {%8,%9}, {%0,%1,%2,%3};" \
        : "+f"((c)[0]), "+f"((c)[1]), "+f"((c)[2]), "+f"((c)[3]) \
        : "r"((a)[0]), "r"((a)[1]), "r"((a)[2]), "r"((a)[3]), \
          "r"((b)[0]), "r"((b)[1]))

#define LDSM_X4(r0, r1, r2, r3, addr) \
    asm volatile("ldmatrix.sync.aligned.m8n8.x4.shared.b16 {%0,%1,%2,%3}, [%4];" \
        : "=r"(r0), "=r"(r1), "=r"(r2), "=r"(r3) : "r"(addr))

#define LDSM_X2T(r0, r1, addr) \
    asm volatile("ldmatrix.sync.aligned.m8n8.x2.trans.shared.b16 {%0,%1}, [%2];" \
        : "=r"(r0), "=r"(r1) : "r"(addr))

// ---------------------------------------------------------------------------
// Generic fp32 -> bf16 hi/lo split (memory-bound)
// ---------------------------------------------------------------------------
__global__ __launch_bounds__(256) void split_f32_kernel(
    const float* __restrict__ in, __nv_bfloat16* __restrict__ hi,
    __nv_bfloat16* __restrict__ lo, int n4)
{
    int i = blockIdx.x * 256 + threadIdx.x;
    if (i >= n4) return;
    float4 v = ((const float4*)in)[i];
    float h0 = bf_round(v.x), h1 = bf_round(v.y);
    float h2 = bf_round(v.z), h3 = bf_round(v.w);
    uint2 hp, lp;
    hp.x = pack_bf16(h0, h1);
    hp.y = pack_bf16(h2, h3);
    lp.x = pack_bf16(v.x - h0, v.y - h1);
    lp.y = pack_bf16(v.z - h2, v.w - h3);
    ((uint2*)hi)[i] = hp;
    ((uint2*)lo)[i] = lp;
}

// ---------------------------------------------------------------------------
// Transpose + split: in [R][C] fp32 -> hi/lo [C][R] bf16. 32x32 smem tiles.
// ---------------------------------------------------------------------------
__global__ __launch_bounds__(256) void transpose_split_kernel(
    const float* __restrict__ in, __nv_bfloat16* __restrict__ hi,
    __nv_bfloat16* __restrict__ lo, int R, int C)
{
    __shared__ float tile[32][33];
    const int tx = threadIdx.x & 31;
    const int ty = threadIdx.x >> 5;
    const int bx = blockIdx.x * 32;  // C offset
    const int by = blockIdx.y * 32;  // R offset

    #pragma unroll
    for (int i = 0; i < 4; i++)
        tile[ty + i * 8][tx] = in[(size_t)(by + ty + i * 8) * C + bx + tx];
    __syncthreads();

    #pragma unroll
    for (int i = 0; i < 4; i++) {
        int r = by + tx;
        int c = bx + ty + i * 8;
        float v = tile[tx][ty + i * 8];
        float h = bf_round(v);
        hi[(size_t)c * R + r] = __float2bfloat16(h);
        lo[(size_t)c * R + r] = __float2bfloat16(v - h);
    }
}

// ---------------------------------------------------------------------------
// GEMM: C[M,N] = A[M,K] @ B'[N,K]^T, fp32 out. CTA tile 128(M) x 256(N).
// TC path: tcgen05 SS-mode, BK=64, SW128, depth-2 with shifted buffer-reuse
// wait (wait MMA(c-1) at iter c — one iteration old, free) so MMA issue and
// loads overlap. Fallback: mma.sync bf16x3 for the non-arch-specific pass.
// ---------------------------------------------------------------------------
#define TCG_PART   16384                 // 128 rows x 128B
#define TCG_STAGE  (6 * TCG_PART)        // Ah Al B0h B0l B1h B1l = 96KB
#define TCG_SMEM   (1024 + 2 * TCG_STAGE)

#if TC_OK
__device__ __forceinline__ void tc_mbar_wait(uint32_t mbar, uint32_t parity) {
    asm volatile(
        "{\n\t.reg .pred P;\n\t"
        "W%=:\n\t"
        "mbarrier.try_wait.parity.shared.b64 P, [%0], %1, 0x989680;\n\t"
        "@P bra D%=;\n\t"
        "bra W%=;\n\t"
        "D%=:\n\t}"
        :: "r"(mbar), "r"(parity) : "memory");
}
__device__ __forceinline__ uint64_t sw128_desc(uint32_t addr) {
    return ((uint64_t)2 << 61) | ((uint64_t)1 << 46)
         | ((uint64_t)64 << 32) | ((uint64_t)1 << 16)
         | ((addr >> 4) & 0x3FFF);
}
__device__ __forceinline__ void tc_mma_f16_ss(
    uint32_t d, uint64_t a, uint64_t b, uint32_t idesc, uint32_t en) {
    asm volatile(
        "{\n\t.reg .pred p;\n\tsetp.ne.u32 p, %4, 0;\n\t"
        "tcgen05.mma.cta_group::1.kind::f16 [%0], %1, %2, %3, {%5,%5,%5,%5}, p;\n\t}"
        :: "r"(d), "l"(a), "l"(b), "r"(idesc), "r"(en), "r"(0u) : "memory");
}
// idesc kind::f16: fp32 accum (bit4), bf16 a/b (bits7,10), N=128, M=128
#define TC_IDESC ((1u << 4) | (1u << 7) | (1u << 10) | (16u << 17) | (8u << 24))
#define TC_LD_X32(r, addr) \
    asm volatile("tcgen05.ld.sync.aligned.32x32b.x32.b32 " \
        "{%0, %1, %2, %3, %4, %5, %6, %7, %8, %9, %10, %11, %12, %13, %14, %15, " \
        " %16, %17, %18, %19, %20, %21, %22, %23, %24, %25, %26, %27, %28, %29, %30, %31}, [%32];" \
        : "=r"((r)[0]), "=r"((r)[1]), "=r"((r)[2]), "=r"((r)[3]), \
          "=r"((r)[4]), "=r"((r)[5]), "=r"((r)[6]), "=r"((r)[7]), \
          "=r"((r)[8]), "=r"((r)[9]), "=r"((r)[10]), "=r"((r)[11]), \
          "=r"((r)[12]), "=r"((r)[13]), "=r"((r)[14]), "=r"((r)[15]), \
          "=r"((r)[16]), "=r"((r)[17]), "=r"((r)[18]), "=r"((r)[19]), \
          "=r"((r)[20]), "=r"((r)[21]), "=r"((r)[22]), "=r"((r)[23]), \
          "=r"((r)[24]), "=r"((r)[25]), "=r"((r)[26]), "=r"((r)[27]), \
          "=r"((r)[28]), "=r"((r)[29]), "=r"((r)[30]), "=r"((r)[31]) \
        : "r"(addr))
#endif

__global__ __launch_bounds__(256, 1) void tc_gemm_kernel(
    const __nv_bfloat16* __restrict__ Ah, const __nv_bfloat16* __restrict__ Al,
    const __nv_bfloat16* __restrict__ Bh, const __nv_bfloat16* __restrict__ Bl,
    float* __restrict__ C, int M, int N, int K)
{
    extern __shared__ char ts[];
#if TC_OK
    // ======================= tcgen05 path (sm_103a) =======================
    const uint32_t base = s2u(ts);
    const int tid  = threadIdx.x;
    const int wid  = tid >> 5;
    const int lane = tid & 31;
    const int brow = blockIdx.y * 128;
    const int bcol = blockIdx.x * 256;
    const int nch  = K >> 6;

    const uint32_t TMEM_PTR = base;
    const uint32_t MBAR     = base + 8;      // two 8B mbarriers
    const uint32_t STG0     = base + 1024;

    const __nv_bfloat16* srcs[6];
    srcs[0] = Ah + (size_t)brow * K;
    srcs[1] = Al + (size_t)brow * K;
    srcs[2] = Bh + (size_t)bcol * K;
    srcs[3] = Bl + (size_t)bcol * K;
    srcs[4] = Bh + (size_t)(bcol + 128) * K;
    srcs[5] = Bl + (size_t)(bcol + 128) * K;

    auto load_chunk = [&](int c) {
        uint32_t st = STG0 + (uint32_t)(c & 1) * TCG_STAGE;
        int k0 = c * 64;
        #pragma unroll
        for (int p = 0; p < 6; p++) {
            #pragma unroll
            for (int i = 0; i < 4; i++) {
                int idx = tid + i * 256;
                int row = idx >> 3;
                int c16 = idx & 7;
                uint32_t dst = st + p * TCG_PART + row * 128
                             + (uint32_t)((c16 ^ (row & 7)) << 4);
                cp16(dst, srcs[p] + (size_t)row * K + k0 + c16 * 8);
            }
        }
    };

    // prologue: two chunks in flight
    load_chunk(0); CP_COMMIT;
    load_chunk(1); CP_COMMIT;

    if (wid == 0) {
        asm volatile("tcgen05.alloc.cta_group::1.sync.aligned.shared::cta.b32 [%0], %1;"
                     :: "r"(TMEM_PTR), "r"(256) : "memory");
    }
    if (tid == 0) {
        asm volatile("mbarrier.init.shared.b64 [%0], %1;" :: "r"(MBAR), "r"(1) : "memory");
        asm volatile("mbarrier.init.shared.b64 [%0], %1;" :: "r"(MBAR + 8), "r"(1) : "memory");
    }
    __syncthreads();
    uint32_t tbase;
    asm volatile("ld.shared.b32 %0, [%1];" : "=r"(tbase) : "r"(TMEM_PTR));
    const uint32_t d0 = tbase, d1 = tbase + 128;

    for (int c = 0; c < nch; c++) {
        // (a) shifted buffer-reuse: load(c+1) overwrites MMA(c-1)'s buffer;
        //     that MMA was committed a full iteration ago -> wait is ~free.
        if (c >= 1 && c + 1 < nch) {
            tc_mbar_wait(MBAR + (uint32_t)((c - 1) & 1) * 8,
                         (uint32_t)(((c - 1) >> 1) & 1));
            load_chunk(c + 1);
            CP_COMMIT;
        }

        // (b) ensure load(c) landed (the newer group may stay pending)
        if (c + 1 < nch) { CP_WAIT(1); } else { CP_WAIT(0); }
        __syncthreads();

        // (c) issue the chunk's MMAs
        if (tid == 0) {
            asm volatile("fence.proxy.async;" ::: "memory");
            uint32_t st = STG0 + (uint32_t)(c & 1) * TCG_STAGE;
            uint64_t aH  = sw128_desc(st);
            uint64_t aL  = sw128_desc(st + TCG_PART);
            uint64_t b0h = sw128_desc(st + 2 * TCG_PART);
            uint64_t b0l = sw128_desc(st + 3 * TCG_PART);
            uint64_t b1h = sw128_desc(st + 4 * TCG_PART);
            uint64_t b1l = sw128_desc(st + 5 * TCG_PART);
            #pragma unroll
            for (int ks = 0; ks < 4; ks++) {
                uint32_t en0 = (c == 0 && ks == 0) ? 0u : 1u;
                uint64_t o = (uint64_t)(ks * 2);
                tc_mma_f16_ss(d0, aH + o, b0h + o, TC_IDESC, en0);
                tc_mma_f16_ss(d0, aH + o, b0l + o, TC_IDESC, 1u);
                tc_mma_f16_ss(d0, aL + o, b0h + o, TC_IDESC, 1u);
                tc_mma_f16_ss(d1, aH + o, b1h + o, TC_IDESC, en0);
                tc_mma_f16_ss(d1, aH + o, b1l + o, TC_IDESC, 1u);
                tc_mma_f16_ss(d1, aL + o, b1h + o, TC_IDESC, 1u);
            }
            asm volatile(
                "tcgen05.commit.cta_group::1.mbarrier::arrive::one.shared::cluster.b64 [%0];"
                :: "r"(MBAR + (uint32_t)(c & 1) * 8) : "memory");
        }
    }

    // final wait: last chunk's commit covers all prior MMAs
    tc_mbar_wait(MBAR + (uint32_t)((nch - 1) & 1) * 8,
                 (uint32_t)(((nch - 1) >> 1) & 1));
    asm volatile("tcgen05.fence::after_thread_sync;" ::: "memory");

    // epilogue: warp w reads rows (w&3)*32, cols (w>>2)*64, both D tiles
    {
        const int row = brow + (wid & 3) * 32 + lane;
        #pragma unroll
        for (int t = 0; t < 2; t++) {
            #pragma unroll
            for (int hlf = 0; hlf < 2; hlf++) {
                uint32_t col = (uint32_t)(t * 128 + (wid >> 2) * 64 + hlf * 32);
                uint32_t r[32];
                TC_LD_X32(r, tbase + col);
                asm volatile("tcgen05.wait::ld.sync.aligned;" ::: "memory");
                float* cp = C + (size_t)row * N + bcol + col;
                #pragma unroll
                for (int j = 0; j < 8; j++) {
                    float4 v = make_float4(__uint_as_float(r[4 * j]),
                                           __uint_as_float(r[4 * j + 1]),
                                           __uint_as_float(r[4 * j + 2]),
                                           __uint_as_float(r[4 * j + 3]));
                    *(float4*)(cp + 4 * j) = v;
                }
            }
        }
    }

    __syncthreads();
    if (wid == 0) {
        asm volatile("tcgen05.relinquish_alloc_permit.cta_group::1.sync.aligned;");
        asm volatile("tcgen05.dealloc.cta_group::1.sync.aligned.b32 %0, %1;"
                     :: "r"(tbase), "r"(256));
    }
#else
    // =================== mma.sync fallback (compute_103) ===================
    const int tid  = threadIdx.x;
    const int lane = tid & 31;
    const int wid  = tid >> 5;
    const int brow = blockIdx.y * 128;
    const int wm   = (wid >> 2) * 64;
    const int wn   = (wid & 3) * 32;
    const uint32_t gs_u = s2u(ts);
    const int nchunks = K / 32;

    const int fr  = (lane & 7) + ((lane >> 4) & 1) * 8;
    const int fc8 = ((lane >> 3) & 1) << 3;

    #pragma unroll 1
    for (int half = 0; half < 2; half++) {
        const int bcol = blockIdx.x * 256 + half * 128;

        auto load_stage = [&](int chunk, int s) {
            uint32_t st = gs_u + (uint32_t)s * 40960;
            int k0 = chunk * 32;
            #pragma unroll
            for (int t = 0; t < 2; t++) {
                int idx = tid + t * 256;
                int r = idx >> 2, c4 = idx & 3;
                size_t ga = (size_t)(brow + r) * K + k0 + c4 * 8;
                size_t gb = (size_t)(bcol + r) * K + k0 + c4 * 8;
                uint32_t off = (uint32_t)(r * 80 + c4 * 16);
                cp16(st + off,             Ah + ga);
                cp16(st + 10240 + off,     Al + ga);
                cp16(st + 2 * 10240 + off, Bh + gb);
                cp16(st + 3 * 10240 + off, Bl + gb);
            }
        };

        float acc[4][4][4];
        #pragma unroll
        for (int i = 0; i < 4; i++)
            #pragma unroll
            for (int j = 0; j < 4; j++)
                #pragma unroll
                for (int r = 0; r < 4; r++) acc[i][j][r] = 0.f;

        load_stage(0, 0);
        CP_COMMIT;

        for (int c = 0; c < nchunks; c++) {
            if (c + 1 < nchunks) {
                load_stage(c + 1, (c + 1) & 1);
                CP_COMMIT;
                CP_WAIT(1);
            } else {
                CP_WAIT(0);
            }
            __syncthreads();

            uint32_t sa = gs_u + (uint32_t)(c & 1) * 40960;
            uint32_t sb = sa + 2 * 10240;

            #pragma unroll
            for (int ks = 0; ks < 2; ks++) {
                const int kb = ks * 16;
                uint32_t bhf[4][2], blf[4][2];
                #pragma unroll
                for (int jj = 0; jj < 2; jj++) {
                    uint32_t ad = sb + (wn + jj * 16 + fr) * 80 + (kb + fc8) * 2;
                    uint32_t tq[4], uq[4];
                    LDSM_X4(tq[0], tq[1], tq[2], tq[3], ad);
                    LDSM_X4(uq[0], uq[1], uq[2], uq[3], ad + 10240);
                    bhf[2 * jj][0] = tq[0]; bhf[2 * jj][1] = tq[1];
                    bhf[2 * jj + 1][0] = tq[2]; bhf[2 * jj + 1][1] = tq[3];
                    blf[2 * jj][0] = uq[0]; blf[2 * jj][1] = uq[1];
                    blf[2 * jj + 1][0] = uq[2]; blf[2 * jj + 1][1] = uq[3];
                }
                #pragma unroll
                for (int i = 0; i < 4; i++) {
                    uint32_t ahf[4], alf[4];
                    uint32_t ad = sa + (wm + i * 16 + (lane & 15)) * 80
                                + (kb + ((lane >> 4) << 3)) * 2;
                    LDSM_X4(ahf[0], ahf[1], ahf[2], ahf[3], ad);
                    LDSM_X4(alf[0], alf[1], alf[2], alf[3], ad + 10240);
                    #pragma unroll
                    for (int j = 0; j < 4; j++) {
                        MMA_BF16(acc[i][j], ahf, bhf[j]);
                        MMA_BF16(acc[i][j], ahf, blf[j]);
                        MMA_BF16(acc[i][j], alf, bhf[j]);
                    }
                }
            }
            __syncthreads();
        }

        const int grp = lane >> 2;
        const int tig = lane & 3;
        #pragma unroll
        for (int i = 0; i < 4; i++) {
            #pragma unroll
            for (int j = 0; j < 4; j++) {
                int row = brow + wm + i * 16 + grp;
                int col = bcol + wn + j * 8 + tig * 2;
                float* c0 = &C[(size_t)row * N + col];
                c0[0] = acc[i][j][0];
                c0[1] = acc[i][j][1];
                float* c1 = c0 + (size_t)8 * N;
                c1[0] = acc[i][j][2];
                c1[1] = acc[i][j][3];
            }
        }
        __syncthreads();
    }
#endif
}

// ---------------------------------------------------------------------------
// RMSNorm+RoPE split kernel (unchanged)
// ---------------------------------------------------------------------------
__global__ __launch_bounds__(256) void split_kernel(
    const float* __restrict__ qkv, const float* __restrict__ cosb,
    const float* __restrict__ sinb, const float* __restrict__ qw,
    const float* __restrict__ kw, __nv_bfloat16* __restrict__ gh,
    __nv_bfloat16* __restrict__ gl)
{
    const int blk = blockIdx.x;
    const int h32 = blk & 31;
    const int bs  = blk >> 5;
    const int tid = threadIdx.x;

    const size_t base = (size_t)bs * F_ + h32 * HD_;
    float x = qkv[base + tid];
    float val;

    if (h32 < NH_ + NKV_) {
        float ss = x * x;
        #pragma unroll
        for (int m = 16; m; m >>= 1) ss += __shfl_xor_sync(~0u, ss, m);
        __shared__ float warpsum[8];
        __shared__ float xn_s[HD_];
        if ((tid & 31) == 0) warpsum[tid >> 5] = ss;
        __syncthreads();
        float tot = warpsum[0] + warpsum[1] + warpsum[2] + warpsum[3]
                  + warpsum[4] + warpsum[5] + warpsum[6] + warpsum[7];
        float inv = rsqrtf(tot * (1.0f / HD_) + EPS_);
        const float* w = (h32 < NH_) ? qw : kw;
        float xn = x * inv * (1.0f + w[tid]);
        xn_s[tid] = xn;
        __syncthreads();
        float rot = (tid < HD_ / 2) ? -xn_s[tid + HD_ / 2] : xn_s[tid - HD_ / 2];
        float c = cosb[(size_t)bs * HD_ + tid];
        float s = sinb[(size_t)bs * HD_ + tid];
        val = xn * c + rot * s;
        if (h32 < NH_) val *= SCALE_;
    } else {
        val = x;
    }

    __nv_bfloat16 hi = __float2bfloat16(val);
    gh[base + tid] = hi;
    gl[base + tid] = __float2bfloat16(val - __bfloat162float(hi));
}

// ---------------------------------------------------------------------------
// MMA flash attention (R13: fixed-max softmax; x2.trans V; bf16 epilogue)
// ---------------------------------------------------------------------------
#define QSTR 264
#define TK 32
#define NT_ (S_ / TK)
#define FATTN_SMEM ((128 * QSTR * 2 + TK * QSTR * 4) * 2)

__global__ __launch_bounds__(256, 1) void fattn_kernel(
    const __nv_bfloat16* __restrict__ gh, const __nv_bfloat16* __restrict__ gl,
    __nv_bfloat16* __restrict__ aoh, __nv_bfloat16* __restrict__ aol)
{
    extern __shared__ __nv_bfloat16 sm[];
    __nv_bfloat16* QH = sm;
    __nv_bfloat16* QL = QH + 128 * QSTR;
    __nv_bfloat16* KH = QL + 128 * QSTR;
    __nv_bfloat16* KL = KH + TK * QSTR;
    __nv_bfloat16* VH = KL + TK * QSTR;
    __nv_bfloat16* VL = VH + TK * QSTR;

    const int tid = threadIdx.x;
    const int w = tid >> 5;
    const int l = tid & 31;

    const int qt = blockIdx.x & 15;
    const int h  = (blockIdx.x >> 4) & 15;
    const int b  = blockIdx.x >> 8;
    const int kvh = h >> 1;
    const int q0 = qt * 128;

    const size_t koff = (size_t)NH_ * HD_ + kvh * HD_;
    const size_t voff = (size_t)(NH_ + NKV_) * HD_ + kvh * HD_;

    for (int i = tid; i < 128 * 32; i += 256) {
        int r = i >> 5, c = i & 31;
        size_t src = ((size_t)(b * S_ + q0 + r)) * F_ + h * HD_ + c * 8;
        int dst = r * QSTR + c * 8;
        *(uint4*)(QH + dst) = *(const uint4*)(gh + src);
        *(uint4*)(QL + dst) = *(const uint4*)(gl + src);
    }
    __syncthreads();

    float o[32][4];
    #pragma unroll
    for (int nt = 0; nt < 32; nt++)
        #pragma unroll
        for (int j = 0; j < 4; j++) o[nt][j] = 0.f;

    float l_lo = 0.f, l_hi = 0.f;

    const uint32_t qh_b = s2u(QH), ql_b = s2u(QL);
    const uint32_t kh_b = s2u(KH), kl_b = s2u(KL);
    const uint32_t vh_b = s2u(VH), vl_b = s2u(VL);

    const int qrow  = 16 * w + (l & 15);
    const int qcol8 = (l >> 4) << 3;
    const int krow  = (l & 7) + ((l >> 4) & 1) * 8;
    const int kcol8 = ((l >> 3) & 1) << 3;
    const int vrow  = l & 15;

    for (int kt = 0; kt < NT_; kt++) {
        __syncthreads();
        for (int i = tid; i < TK * 32; i += 256) {
            int r = i >> 5, c = i & 31;
            size_t base = ((size_t)(b * S_ + kt * TK + r)) * F_;
            int dst = r * QSTR + c * 8;
            *(uint4*)(KH + dst) = *(const uint4*)(gh + base + koff + c * 8);
            *(uint4*)(KL + dst) = *(const uint4*)(gl + base + koff + c * 8);
            *(uint4*)(VH + dst) = *(const uint4*)(gh + base + voff + c * 8);
            *(uint4*)(VL + dst) = *(const uint4*)(gl + base + voff + c * 8);
        }
        __syncthreads();

        float sA[4][4];
        #pragma unroll
        for (int nt = 0; nt < 4; nt++)
            #pragma unroll
            for (int j = 0; j < 4; j++) sA[nt][j] = 0.f;

        #pragma unroll
        for (int ks = 0; ks < 16; ks++) {
            uint32_t ah[4], al[4];
            uint32_t qoff = (uint32_t)(qrow * QSTR + ks * 16 + qcol8) * 2;
            LDSM_X4(ah[0], ah[1], ah[2], ah[3], qh_b + qoff);
            LDSM_X4(al[0], al[1], al[2], al[3], ql_b + qoff);
            #pragma unroll
            for (int ntp = 0; ntp < 2; ntp++) {
                uint32_t bh[4], bl[4];
                uint32_t kofs = (uint32_t)((16 * ntp + krow) * QSTR + ks * 16 + kcol8) * 2;
                LDSM_X4(bh[0], bh[1], bh[2], bh[3], kh_b + kofs);
                LDSM_X4(bl[0], bl[1], bl[2], bl[3], kl_b + kofs);
                MMA_BF16(sA[2 * ntp],     ah, bh);
                MMA_BF16(sA[2 * ntp],     ah, bl);
                MMA_BF16(sA[2 * ntp],     al, bh);
                MMA_BF16(sA[2 * ntp + 1], ah, bh + 2);
                MMA_BF16(sA[2 * ntp + 1], ah, bl + 2);
                MMA_BF16(sA[2 * ntp + 1], al, bh + 2);
            }
        }

        // fixed-max softmax: P = exp(S - 6)
        #pragma unroll
        for (int nt = 0; nt < 4; nt++) {
            sA[nt][0] = ex2f(fmaf(sA[nt][0], LOG2E_, -MSHIFT_));
            sA[nt][1] = ex2f(fmaf(sA[nt][1], LOG2E_, -MSHIFT_));
            sA[nt][2] = ex2f(fmaf(sA[nt][2], LOG2E_, -MSHIFT_));
            sA[nt][3] = ex2f(fmaf(sA[nt][3], LOG2E_, -MSHIFT_));
            l_lo += sA[nt][0] + sA[nt][1];
            l_hi += sA[nt][2] + sA[nt][3];
        }

        uint32_t aPh[2][4], aPl[2][4];
        #pragma unroll
        for (int ksp = 0; ksp < 2; ksp++) {
            #pragma unroll
            for (int q = 0; q < 4; q++) {
                int nt = 2 * ksp + (q >> 1);
                int j0 = (q & 1) * 2;
                float p0 = sA[nt][j0], p1 = sA[nt][j0 + 1];
                float h0 = bf_round(p0), h1 = bf_round(p1);
                aPh[ksp][q] = pack_bf16(h0, h1);
                aPl[ksp][q] = pack_bf16(p0 - h0, p1 - h1);
            }
        }

        #pragma unroll
        for (int ksp = 0; ksp < 2; ksp++) {
            #pragma unroll
            for (int nt = 0; nt < 32; nt++) {
                uint32_t vofs = (uint32_t)((16 * ksp + vrow) * QSTR + nt * 8) * 2;
                uint32_t bv[2], bw[2];
                LDSM_X2T(bv[0], bv[1], vh_b + vofs);
                LDSM_X2T(bw[0], bw[1], vl_b + vofs);
                MMA_BF16(o[nt], aPh[ksp], bv);
                MMA_BF16(o[nt], aPh[ksp], bw);
                MMA_BF16(o[nt], aPl[ksp], bv);
            }
        }
    }

    l_lo += __shfl_xor_sync(~0u, l_lo, 1);
    l_lo += __shfl_xor_sync(~0u, l_lo, 2);
    l_hi += __shfl_xor_sync(~0u, l_hi, 1);
    l_hi += __shfl_xor_sync(~0u, l_hi, 2);

    float inv_lo = 1.0f / l_lo;
    float inv_hi = 1.0f / l_hi;
    const int row_lo = q0 + 16 * w + (l >> 2);
    const int col0 = h * HD_ + 2 * (l & 3);
    #pragma unroll
    for (int nt = 0; nt < 32; nt++) {
        float v0 = o[nt][0] * inv_lo, v1 = o[nt][1] * inv_lo;
        float v2 = o[nt][2] * inv_hi, v3 = o[nt][3] * inv_hi;
        float h0 = bf_round(v0), h1 = bf_round(v1);
        float h2 = bf_round(v2), h3 = bf_round(v3);
        size_t i0 = (size_t)(b * S_ + row_lo)     * (NH_ * HD_) + col0 + nt * 8;
        size_t i1 = (size_t)(b * S_ + row_lo + 8) * (NH_ * HD_) + col0 + nt * 8;
        *(uint32_t*)(aoh + i0) = pack_bf16(h0, h1);
        *(uint32_t*)(aol + i0) = pack_bf16(v0 - h0, v1 - h1);
        *(uint32_t*)(aoh + i1) = pack_bf16(h2, h3);
        *(uint32_t*)(aol + i1) = pack_bf16(v2 - h2, v3 - h3);
    }
}

// ---------------------------------------------------------------------------
// Launch
// ---------------------------------------------------------------------------
extern "C" void kernel_launch(void* const* d_in, const int* in_sizes, int n_in,
                              void* d_out, int out_size)
{
    const float* hidden = (const float*)d_in[0];
    const float* cosb   = (const float*)d_in[1];
    const float* sinb   = (const float*)d_in[2];
    const float* w_qkv  = (const float*)d_in[3];
    const float* w_o    = (const float*)d_in[4];
    const float* q_w    = (const float*)d_in[5];
    const float* k_w    = (const float*)d_in[6];
    float* out = (float*)d_out;

    float* qkv; cudaGetSymbolAddress((void**)&qkv, g_qkv);
    __nv_bfloat16 *gh, *gl, *hidh, *hidl, *wqh, *wql, *woh, *wol, *aoh, *aol;
    cudaGetSymbolAddress((void**)&gh,   g_h);
    cudaGetSymbolAddress((void**)&gl,   g_l);
    cudaGetSymbolAddress((void**)&hidh, g_hidh);
    cudaGetSymbolAddress((void**)&hidl, g_hidl);
    cudaGetSymbolAddress((void**)&wqh,  g_wqh);
    cudaGetSymbolAddress((void**)&wql,  g_wql);
    cudaGetSymbolAddress((void**)&woh,  g_woh);
    cudaGetSymbolAddress((void**)&wol,  g_wol);
    cudaGetSymbolAddress((void**)&aoh,  g_aoh);
    cudaGetSymbolAddress((void**)&aol,  g_aol);

    cudaFuncSetAttribute(fattn_kernel, cudaFuncAttributeMaxDynamicSharedMemorySize,
                         FATTN_SMEM);
    cudaFuncSetAttribute(tc_gemm_kernel, cudaFuncAttributeMaxDynamicSharedMemorySize,
                         TCG_SMEM);

    // 0) Split hidden; transpose+split weights to [N][K]
    {
        int n4 = M1_ * HID_ / 4;
        split_f32_kernel<<<(n4 + 255) / 256, 256>>>(hidden, hidh, hidl, n4);
        dim3 gq(F_ / 32, HID_ / 32);
        transpose_split_kernel<<<gq, 256>>>(w_qkv, wqh, wql, HID_, F_);
        dim3 go(HID_ / 32, (NH_ * HD_) / 32);
        transpose_split_kernel<<<go, 256>>>(w_o, woh, wol, NH_ * HD_, HID_);
    }

    // 1) QKV projection: [4096,2048] @ [2048,8192]
    {
        dim3 grid(F_ / 256, M1_ / 128);
        tc_gemm_kernel<<<grid, 256, TCG_SMEM>>>(hidh, hidl, wqh, wql,
                                                qkv, M1_, F_, HID_);
    }

    // 2) RMSNorm + RoPE + bf16 hi/lo split for attention
    split_kernel<<<M1_ * 32, 256>>>(qkv, cosb, sinb, q_w, k_w, gh, gl);

    // 3) Flash attention (tensor cores) -> writes bf16 hi/lo O-proj input
    fattn_kernel<<<B_ * NH_ * (S_ / 128), 256, FATTN_SMEM>>>(gh, gl, aoh, aol);

    // 4) Output projection: [4096,4096] @ [4096,2048]
    {
        dim3 grid(HID_ / 256, M1_ / 128);
        tc_gemm_kernel<<<grid, 256, TCG_SMEM>>>(aoh, aol, woh, wol,
                                                out, M1_, HID_, NH_ * HD_);
    }
}

// round 17
// speedup vs baseline: 1.0077x; 1.0003x over previous
#include <cuda_runtime.h>
#include <cuda_bf16.h>
#include <math.h>
#include <stdint.h>

// Problem constants
#define B_   2
#define S_   2048
#define HID_ 2048
#define NH_  16
#define NKV_ 8
#define HD_  256
#define F_   8192      // (NH + 2*NKV) * HD
#define M1_  4096      // B*S
#define EPS_ 1e-6f
#define SCALE_ 0.0625f // 256^-0.5
#define LOG2E_ 1.4426950408889634f
#define MSHIFT_ (6.0f * LOG2E_)   // fixed softmax shift (|S| <= 16, safe)

// Arch-specific feature gate: tcgen05 only exists on sm_103a/f passes.
#if defined(__CUDA_ARCH_FEAT_SM103_ALL) || defined(__CUDA_ARCH_SPECIFIC__) || defined(__CUDA_ARCH_FAMILY_SPECIFIC__)
#define TC_OK 1
#else
#define TC_OK 0
#endif

// Scratch (device globals, no allocation)
__device__ float g_qkv[(size_t)M1_ * F_];          // qkv projection (fp32)
__device__ __nv_bfloat16 g_h[(size_t)M1_ * F_];    // attn operands hi split
__device__ __nv_bfloat16 g_l[(size_t)M1_ * F_];    // attn operands lo split
// GEMM operand splits. Weights stored TRANSPOSED: [N][K] K-major.
__device__ __nv_bfloat16 g_hidh[(size_t)M1_ * HID_];
__device__ __nv_bfloat16 g_hidl[(size_t)M1_ * HID_];
__device__ __nv_bfloat16 g_wqh [(size_t)F_ * HID_];          // [F][HID]
__device__ __nv_bfloat16 g_wql [(size_t)F_ * HID_];
__device__ __nv_bfloat16 g_woh [(size_t)HID_ * (NH_*HD_)];   // [HID][NH*HD]
__device__ __nv_bfloat16 g_wol [(size_t)HID_ * (NH_*HD_)];
__device__ __nv_bfloat16 g_aoh [(size_t)M1_ * (NH_*HD_)];
__device__ __nv_bfloat16 g_aol [(size_t)M1_ * (NH_*HD_)];

// ---------------------------------------------------------------------------
// helpers (arch-neutral)
// ---------------------------------------------------------------------------
__device__ __forceinline__ uint32_t s2u(const void* p) {
    return (uint32_t)__cvta_generic_to_shared(p);
}
__device__ __forceinline__ float ex2f(float x) {
    float y; asm("ex2.approx.f32 %0, %1;" : "=f"(y) : "f"(x)); return y;
}
__device__ __forceinline__ uint32_t pack_bf16(float lo, float hi) {
    uint32_t r;
    asm("cvt.rn.bf16x2.f32 %0, %1, %2;" : "=r"(r) : "f"(hi), "f"(lo));
    return r;
}
__device__ __forceinline__ float bf_round(float x) {
    return __bfloat162float(__float2bfloat16(x));
}
__device__ __forceinline__ void cp16(uint32_t s, const void* g) {
    asm volatile("cp.async.cg.shared.global [%0], [%1], 16;" :: "r"(s), "l"(g));
}
#define CP_COMMIT asm volatile("cp.async.commit_group;")
#define CP_WAIT(n) asm volatile("cp.async.wait_group %0;" :: "n"(n))

#define MMA_BF16(c, a, b) \
    asm volatile("mma.sync.aligned.m16n8k16.row.col.f32.bf16.bf16.f32 " \
        "{%0,%1,%2,%3}, {%4,%5,%6,%7}, {%8,%9}, {%0,%1,%2,%3};" \
        : "+f"((c)[0]), "+f"((c)[1]), "+f"((c)[2]), "+f"((c)[3]) \
        : "r"((a)[0]), "r"((a)[1]), "r"((a)[2]), "r"((a)[3]), \
          "r"((b)[0]), "r"((b)[1]))

#define LDSM_X4(r0, r1, r2, r3, addr) \
    asm volatile("ldmatrix.sync.aligned.m8n8.x4.shared.b16 {%0,%1,%2,%3}, [%4];" \
        : "=r"(r0), "=r"(r1), "=r"(r2), "=r"(r3) : "r"(addr))

#define LDSM_X2T(r0, r1, addr) \
    asm volatile("ldmatrix.sync.aligned.m8n8.x2.trans.shared.b16 {%0,%1}, [%2];" \
        : "=r"(r0), "=r"(r1) : "r"(addr))

// ---------------------------------------------------------------------------
// Generic fp32 -> bf16 hi/lo split (memory-bound)
// ---------------------------------------------------------------------------
__global__ __launch_bounds__(256) void split_f32_kernel(
    const float* __restrict__ in, __nv_bfloat16* __restrict__ hi,
    __nv_bfloat16* __restrict__ lo, int n4)
{
    int i = blockIdx.x * 256 + threadIdx.x;
    if (i >= n4) return;
    float4 v = ((const float4*)in)[i];
    float h0 = bf_round(v.x), h1 = bf_round(v.y);
    float h2 = bf_round(v.z), h3 = bf_round(v.w);
    uint2 hp, lp;
    hp.x = pack_bf16(h0, h1);
    hp.y = pack_bf16(h2, h3);
    lp.x = pack_bf16(v.x - h0, v.y - h1);
    lp.y = pack_bf16(v.z - h2, v.w - h3);
    ((uint2*)hi)[i] = hp;
    ((uint2*)lo)[i] = lp;
}

// ---------------------------------------------------------------------------
// Transpose + split: in [R][C] fp32 -> hi/lo [C][R] bf16. 32x32 smem tiles.
// ---------------------------------------------------------------------------
__global__ __launch_bounds__(256) void transpose_split_kernel(
    const float* __restrict__ in, __nv_bfloat16* __restrict__ hi,
    __nv_bfloat16* __restrict__ lo, int R, int C)
{
    __shared__ float tile[32][33];
    const int tx = threadIdx.x & 31;
    const int ty = threadIdx.x >> 5;
    const int bx = blockIdx.x * 32;  // C offset
    const int by = blockIdx.y * 32;  // R offset

    #pragma unroll
    for (int i = 0; i < 4; i++)
        tile[ty + i * 8][tx] = in[(size_t)(by + ty + i * 8) * C + bx + tx];
    __syncthreads();

    #pragma unroll
    for (int i = 0; i < 4; i++) {
        int r = by + tx;
        int c = bx + ty + i * 8;
        float v = tile[tx][ty + i * 8];
        float h = bf_round(v);
        hi[(size_t)c * R + r] = __float2bfloat16(h);
        lo[(size_t)c * R + r] = __float2bfloat16(v - h);
    }
}

// ---------------------------------------------------------------------------
// GEMM: C[M,N] = A[M,K] @ B'[N,K]^T, fp32 out. CTA tile 128(M) x 256(N).
// TC path: tcgen05 SS-mode, BK=64, SW128, depth-2 with shifted buffer-reuse
// wait (wait MMA(c-1) at iter c — one iteration old, free) so MMA issue and
// loads overlap. Fallback: mma.sync bf16x3 for the non-arch-specific pass.
// ---------------------------------------------------------------------------
#define TCG_PART   16384                 // 128 rows x 128B
#define TCG_STAGE  (6 * TCG_PART)        // Ah Al B0h B0l B1h B1l = 96KB
#define TCG_SMEM   (1024 + 2 * TCG_STAGE)

#if TC_OK
__device__ __forceinline__ void tc_mbar_wait(uint32_t mbar, uint32_t parity) {
    asm volatile(
        "{\n\t.reg .pred P;\n\t"
        "W%=:\n\t"
        "mbarrier.try_wait.parity.shared.b64 P, [%0], %1, 0x989680;\n\t"
        "@P bra D%=;\n\t"
        "bra W%=;\n\t"
        "D%=:\n\t}"
        :: "r"(mbar), "r"(parity) : "memory");
}
__device__ __forceinline__ uint64_t sw128_desc(uint32_t addr) {
    return ((uint64_t)2 << 61) | ((uint64_t)1 << 46)
         | ((uint64_t)64 << 32) | ((uint64_t)1 << 16)
         | ((addr >> 4) & 0x3FFF);
}
__device__ __forceinline__ void tc_mma_f16_ss(
    uint32_t d, uint64_t a, uint64_t b, uint32_t idesc, uint32_t en) {
    asm volatile(
        "{\n\t.reg .pred p;\n\tsetp.ne.u32 p, %4, 0;\n\t"
        "tcgen05.mma.cta_group::1.kind::f16 [%0], %1, %2, %3, {%5,%5,%5,%5}, p;\n\t}"
        :: "r"(d), "l"(a), "l"(b), "r"(idesc), "r"(en), "r"(0u) : "memory");
}
// idesc kind::f16: fp32 accum (bit4), bf16 a/b (bits7,10), N=128, M=128
#define TC_IDESC ((1u << 4) | (1u << 7) | (1u << 10) | (16u << 17) | (8u << 24))
#define TC_LD_X32(r, addr) \
    asm volatile("tcgen05.ld.sync.aligned.32x32b.x32.b32 " \
        "{%0, %1, %2, %3, %4, %5, %6, %7, %8, %9, %10, %11, %12, %13, %14, %15, " \
        " %16, %17, %18, %19, %20, %21, %22, %23, %24, %25, %26, %27, %28, %29, %30, %31}, [%32];" \
        : "=r"((r)[0]), "=r"((r)[1]), "=r"((r)[2]), "=r"((r)[3]), \
          "=r"((r)[4]), "=r"((r)[5]), "=r"((r)[6]), "=r"((r)[7]), \
          "=r"((r)[8]), "=r"((r)[9]), "=r"((r)[10]), "=r"((r)[11]), \
          "=r"((r)[12]), "=r"((r)[13]), "=r"((r)[14]), "=r"((r)[15]), \
          "=r"((r)[16]), "=r"((r)[17]), "=r"((r)[18]), "=r"((r)[19]), \
          "=r"((r)[20]), "=r"((r)[21]), "=r"((r)[22]), "=r"((r)[23]), \
          "=r"((r)[24]), "=r"((r)[25]), "=r"((r)[26]), "=r"((r)[27]), \
          "=r"((r)[28]), "=r"((r)[29]), "=r"((r)[30]), "=r"((r)[31]) \
        : "r"(addr))
#endif

__global__ __launch_bounds__(256, 1) void tc_gemm_kernel(
    const __nv_bfloat16* __restrict__ Ah, const __nv_bfloat16* __restrict__ Al,
    const __nv_bfloat16* __restrict__ Bh, const __nv_bfloat16* __restrict__ Bl,
    float* __restrict__ C, int M, int N, int K)
{
    extern __shared__ char ts[];
#if TC_OK
    // ======================= tcgen05 path (sm_103a) =======================
    const uint32_t base = s2u(ts);
    const int tid  = threadIdx.x;
    const int wid  = tid >> 5;
    const int lane = tid & 31;
    const int brow = blockIdx.y * 128;
    const int bcol = blockIdx.x * 256;
    const int nch  = K >> 6;

    const uint32_t TMEM_PTR = base;
    const uint32_t MBAR     = base + 8;      // two 8B mbarriers
    const uint32_t STG0     = base + 1024;

    const __nv_bfloat16* srcs[6];
    srcs[0] = Ah + (size_t)brow * K;
    srcs[1] = Al + (size_t)brow * K;
    srcs[2] = Bh + (size_t)bcol * K;
    srcs[3] = Bl + (size_t)bcol * K;
    srcs[4] = Bh + (size_t)(bcol + 128) * K;
    srcs[5] = Bl + (size_t)(bcol + 128) * K;

    auto load_chunk = [&](int c) {
        uint32_t st = STG0 + (uint32_t)(c & 1) * TCG_STAGE;
        int k0 = c * 64;
        #pragma unroll
        for (int p = 0; p < 6; p++) {
            #pragma unroll
            for (int i = 0; i < 4; i++) {
                int idx = tid + i * 256;
                int row = idx >> 3;
                int c16 = idx & 7;
                uint32_t dst = st + p * TCG_PART + row * 128
                             + (uint32_t)((c16 ^ (row & 7)) << 4);
                cp16(dst, srcs[p] + (size_t)row * K + k0 + c16 * 8);
            }
        }
    };

    // prologue: two chunks in flight
    load_chunk(0); CP_COMMIT;
    load_chunk(1); CP_COMMIT;

    if (wid == 0) {
        asm volatile("tcgen05.alloc.cta_group::1.sync.aligned.shared::cta.b32 [%0], %1;"
                     :: "r"(TMEM_PTR), "r"(256) : "memory");
    }
    if (tid == 0) {
        asm volatile("mbarrier.init.shared.b64 [%0], %1;" :: "r"(MBAR), "r"(1) : "memory");
        asm volatile("mbarrier.init.shared.b64 [%0], %1;" :: "r"(MBAR + 8), "r"(1) : "memory");
    }
    __syncthreads();
    uint32_t tbase;
    asm volatile("ld.shared.b32 %0, [%1];" : "=r"(tbase) : "r"(TMEM_PTR));
    const uint32_t d0 = tbase, d1 = tbase + 128;

    for (int c = 0; c < nch; c++) {
        // (a) shifted buffer-reuse: load(c+1) overwrites MMA(c-1)'s buffer;
        //     that MMA was committed a full iteration ago -> wait is ~free.
        if (c >= 1 && c + 1 < nch) {
            tc_mbar_wait(MBAR + (uint32_t)((c - 1) & 1) * 8,
                         (uint32_t)(((c - 1) >> 1) & 1));
            load_chunk(c + 1);
            CP_COMMIT;
        }

        // (b) ensure load(c) landed (the newer group may stay pending)
        if (c + 1 < nch) { CP_WAIT(1); } else { CP_WAIT(0); }
        __syncthreads();

        // (c) issue the chunk's MMAs
        if (tid == 0) {
            asm volatile("fence.proxy.async;" ::: "memory");
            uint32_t st = STG0 + (uint32_t)(c & 1) * TCG_STAGE;
            uint64_t aH  = sw128_desc(st);
            uint64_t aL  = sw128_desc(st + TCG_PART);
            uint64_t b0h = sw128_desc(st + 2 * TCG_PART);
            uint64_t b0l = sw128_desc(st + 3 * TCG_PART);
            uint64_t b1h = sw128_desc(st + 4 * TCG_PART);
            uint64_t b1l = sw128_desc(st + 5 * TCG_PART);
            #pragma unroll
            for (int ks = 0; ks < 4; ks++) {
                uint32_t en0 = (c == 0 && ks == 0) ? 0u : 1u;
                uint64_t o = (uint64_t)(ks * 2);
                tc_mma_f16_ss(d0, aH + o, b0h + o, TC_IDESC, en0);
                tc_mma_f16_ss(d0, aH + o, b0l + o, TC_IDESC, 1u);
                tc_mma_f16_ss(d0, aL + o, b0h + o, TC_IDESC, 1u);
                tc_mma_f16_ss(d1, aH + o, b1h + o, TC_IDESC, en0);
                tc_mma_f16_ss(d1, aH + o, b1l + o, TC_IDESC, 1u);
                tc_mma_f16_ss(d1, aL + o, b1h + o, TC_IDESC, 1u);
            }
            asm volatile(
                "tcgen05.commit.cta_group::1.mbarrier::arrive::one.shared::cluster.b64 [%0];"
                :: "r"(MBAR + (uint32_t)(c & 1) * 8) : "memory");
        }
    }

    // final wait: last chunk's commit covers all prior MMAs
    tc_mbar_wait(MBAR + (uint32_t)((nch - 1) & 1) * 8,
                 (uint32_t)(((nch - 1) >> 1) & 1));
    asm volatile("tcgen05.fence::after_thread_sync;" ::: "memory");

    // epilogue: warp w reads rows (w&3)*32, cols (w>>2)*64, both D tiles
    {
        const int row = brow + (wid & 3) * 32 + lane;
        #pragma unroll
        for (int t = 0; t < 2; t++) {
            #pragma unroll
            for (int hlf = 0; hlf < 2; hlf++) {
                uint32_t col = (uint32_t)(t * 128 + (wid >> 2) * 64 + hlf * 32);
                uint32_t r[32];
                TC_LD_X32(r, tbase + col);
                asm volatile("tcgen05.wait::ld.sync.aligned;" ::: "memory");
                float* cp = C + (size_t)row * N + bcol + col;
                #pragma unroll
                for (int j = 0; j < 8; j++) {
                    float4 v = make_float4(__uint_as_float(r[4 * j]),
                                           __uint_as_float(r[4 * j + 1]),
                                           __uint_as_float(r[4 * j + 2]),
                                           __uint_as_float(r[4 * j + 3]));
                    *(float4*)(cp + 4 * j) = v;
                }
            }
        }
    }

    __syncthreads();
    if (wid == 0) {
        asm volatile("tcgen05.relinquish_alloc_permit.cta_group::1.sync.aligned;");
        asm volatile("tcgen05.dealloc.cta_group::1.sync.aligned.b32 %0, %1;"
                     :: "r"(tbase), "r"(256));
    }
#else
    // =================== mma.sync fallback (compute_103) ===================
    const int tid  = threadIdx.x;
    const int lane = tid & 31;
    const int wid  = tid >> 5;
    const int brow = blockIdx.y * 128;
    const int wm   = (wid >> 2) * 64;
    const int wn   = (wid & 3) * 32;
    const uint32_t gs_u = s2u(ts);
    const int nchunks = K / 32;

    const int fr  = (lane & 7) + ((lane >> 4) & 1) * 8;
    const int fc8 = ((lane >> 3) & 1) << 3;

    #pragma unroll 1
    for (int half = 0; half < 2; half++) {
        const int bcol = blockIdx.x * 256 + half * 128;

        auto load_stage = [&](int chunk, int s) {
            uint32_t st = gs_u + (uint32_t)s * 40960;
            int k0 = chunk * 32;
            #pragma unroll
            for (int t = 0; t < 2; t++) {
                int idx = tid + t * 256;
                int r = idx >> 2, c4 = idx & 3;
                size_t ga = (size_t)(brow + r) * K + k0 + c4 * 8;
                size_t gb = (size_t)(bcol + r) * K + k0 + c4 * 8;
                uint32_t off = (uint32_t)(r * 80 + c4 * 16);
                cp16(st + off,             Ah + ga);
                cp16(st + 10240 + off,     Al + ga);
                cp16(st + 2 * 10240 + off, Bh + gb);
                cp16(st + 3 * 10240 + off, Bl + gb);
            }
        };

        float acc[4][4][4];
        #pragma unroll
        for (int i = 0; i < 4; i++)
            #pragma unroll
            for (int j = 0; j < 4; j++)
                #pragma unroll
                for (int r = 0; r < 4; r++) acc[i][j][r] = 0.f;

        load_stage(0, 0);
        CP_COMMIT;

        for (int c = 0; c < nchunks; c++) {
            if (c + 1 < nchunks) {
                load_stage(c + 1, (c + 1) & 1);
                CP_COMMIT;
                CP_WAIT(1);
            } else {
                CP_WAIT(0);
            }
            __syncthreads();

            uint32_t sa = gs_u + (uint32_t)(c & 1) * 40960;
            uint32_t sb = sa + 2 * 10240;

            #pragma unroll
            for (int ks = 0; ks < 2; ks++) {
                const int kb = ks * 16;
                uint32_t bhf[4][2], blf[4][2];
                #pragma unroll
                for (int jj = 0; jj < 2; jj++) {
                    uint32_t ad = sb + (wn + jj * 16 + fr) * 80 + (kb + fc8) * 2;
                    uint32_t tq[4], uq[4];
                    LDSM_X4(tq[0], tq[1], tq[2], tq[3], ad);
                    LDSM_X4(uq[0], uq[1], uq[2], uq[3], ad + 10240);
                    bhf[2 * jj][0] = tq[0]; bhf[2 * jj][1] = tq[1];
                    bhf[2 * jj + 1][0] = tq[2]; bhf[2 * jj + 1][1] = tq[3];
                    blf[2 * jj][0] = uq[0]; blf[2 * jj][1] = uq[1];
                    blf[2 * jj + 1][0] = uq[2]; blf[2 * jj + 1][1] = uq[3];
                }
                #pragma unroll
                for (int i = 0; i < 4; i++) {
                    uint32_t ahf[4], alf[4];
                    uint32_t ad = sa + (wm + i * 16 + (lane & 15)) * 80
                                + (kb + ((lane >> 4) << 3)) * 2;
                    LDSM_X4(ahf[0], ahf[1], ahf[2], ahf[3], ad);
                    LDSM_X4(alf[0], alf[1], alf[2], alf[3], ad + 10240);
                    #pragma unroll
                    for (int j = 0; j < 4; j++) {
                        MMA_BF16(acc[i][j], ahf, bhf[j]);
                        MMA_BF16(acc[i][j], ahf, blf[j]);
                        MMA_BF16(acc[i][j], alf, bhf[j]);
                    }
                }
            }
            __syncthreads();
        }

        const int grp = lane >> 2;
        const int tig = lane & 3;
        #pragma unroll
        for (int i = 0; i < 4; i++) {
            #pragma unroll
            for (int j = 0; j < 4; j++) {
                int row = brow + wm + i * 16 + grp;
                int col = bcol + wn + j * 8 + tig * 2;
                float* c0 = &C[(size_t)row * N + col];
                c0[0] = acc[i][j][0];
                c0[1] = acc[i][j][1];
                float* c1 = c0 + (size_t)8 * N;
                c1[0] = acc[i][j][2];
                c1[1] = acc[i][j][3];
            }
        }
        __syncthreads();
    }
#endif
}

// ---------------------------------------------------------------------------
// RMSNorm+RoPE split kernel (unchanged)
// ---------------------------------------------------------------------------
__global__ __launch_bounds__(256) void split_kernel(
    const float* __restrict__ qkv, const float* __restrict__ cosb,
    const float* __restrict__ sinb, const float* __restrict__ qw,
    const float* __restrict__ kw, __nv_bfloat16* __restrict__ gh,
    __nv_bfloat16* __restrict__ gl)
{
    const int blk = blockIdx.x;
    const int h32 = blk & 31;
    const int bs  = blk >> 5;
    const int tid = threadIdx.x;

    const size_t base = (size_t)bs * F_ + h32 * HD_;
    float x = qkv[base + tid];
    float val;

    if (h32 < NH_ + NKV_) {
        float ss = x * x;
        #pragma unroll
        for (int m = 16; m; m >>= 1) ss += __shfl_xor_sync(~0u, ss, m);
        __shared__ float warpsum[8];
        __shared__ float xn_s[HD_];
        if ((tid & 31) == 0) warpsum[tid >> 5] = ss;
        __syncthreads();
        float tot = warpsum[0] + warpsum[1] + warpsum[2] + warpsum[3]
                  + warpsum[4] + warpsum[5] + warpsum[6] + warpsum[7];
        float inv = rsqrtf(tot * (1.0f / HD_) + EPS_);
        const float* w = (h32 < NH_) ? qw : kw;
        float xn = x * inv * (1.0f + w[tid]);
        xn_s[tid] = xn;
        __syncthreads();
        float rot = (tid < HD_ / 2) ? -xn_s[tid + HD_ / 2] : xn_s[tid - HD_ / 2];
        float c = cosb[(size_t)bs * HD_ + tid];
        float s = sinb[(size_t)bs * HD_ + tid];
        val = xn * c + rot * s;
        if (h32 < NH_) val *= SCALE_;
    } else {
        val = x;
    }

    __nv_bfloat16 hi = __float2bfloat16(val);
    gh[base + tid] = hi;
    gl[base + tid] = __float2bfloat16(val - __bfloat162float(hi));
}

// ---------------------------------------------------------------------------
// MMA flash attention (R13: fixed-max softmax; x2.trans V; bf16 epilogue)
// ---------------------------------------------------------------------------
#define QSTR 264
#define TK 32
#define NT_ (S_ / TK)
#define FATTN_SMEM ((128 * QSTR * 2 + TK * QSTR * 4) * 2)

__global__ __launch_bounds__(256, 1) void fattn_kernel(
    const __nv_bfloat16* __restrict__ gh, const __nv_bfloat16* __restrict__ gl,
    __nv_bfloat16* __restrict__ aoh, __nv_bfloat16* __restrict__ aol)
{
    extern __shared__ __nv_bfloat16 sm[];
    __nv_bfloat16* QH = sm;
    __nv_bfloat16* QL = QH + 128 * QSTR;
    __nv_bfloat16* KH = QL + 128 * QSTR;
    __nv_bfloat16* KL = KH + TK * QSTR;
    __nv_bfloat16* VH = KL + TK * QSTR;
    __nv_bfloat16* VL = VH + TK * QSTR;

    const int tid = threadIdx.x;
    const int w = tid >> 5;
    const int l = tid & 31;

    const int qt = blockIdx.x & 15;
    const int h  = (blockIdx.x >> 4) & 15;
    const int b  = blockIdx.x >> 8;
    const int kvh = h >> 1;
    const int q0 = qt * 128;

    const size_t koff = (size_t)NH_ * HD_ + kvh * HD_;
    const size_t voff = (size_t)(NH_ + NKV_) * HD_ + kvh * HD_;

    for (int i = tid; i < 128 * 32; i += 256) {
        int r = i >> 5, c = i & 31;
        size_t src = ((size_t)(b * S_ + q0 + r)) * F_ + h * HD_ + c * 8;
        int dst = r * QSTR + c * 8;
        *(uint4*)(QH + dst) = *(const uint4*)(gh + src);
        *(uint4*)(QL + dst) = *(const uint4*)(gl + src);
    }
    __syncthreads();

    float o[32][4];
    #pragma unroll
    for (int nt = 0; nt < 32; nt++)
        #pragma unroll
        for (int j = 0; j < 4; j++) o[nt][j] = 0.f;

    float l_lo = 0.f, l_hi = 0.f;

    const uint32_t qh_b = s2u(QH), ql_b = s2u(QL);
    const uint32_t kh_b = s2u(KH), kl_b = s2u(KL);
    const uint32_t vh_b = s2u(VH), vl_b = s2u(VL);

    const int qrow  = 16 * w + (l & 15);
    const int qcol8 = (l >> 4) << 3;
    const int krow  = (l & 7) + ((l >> 4) & 1) * 8;
    const int kcol8 = ((l >> 3) & 1) << 3;
    const int vrow  = l & 15;

    for (int kt = 0; kt < NT_; kt++) {
        __syncthreads();
        for (int i = tid; i < TK * 32; i += 256) {
            int r = i >> 5, c = i & 31;
            size_t base = ((size_t)(b * S_ + kt * TK + r)) * F_;
            int dst = r * QSTR + c * 8;
            *(uint4*)(KH + dst) = *(const uint4*)(gh + base + koff + c * 8);
            *(uint4*)(KL + dst) = *(const uint4*)(gl + base + koff + c * 8);
            *(uint4*)(VH + dst) = *(const uint4*)(gh + base + voff + c * 8);
            *(uint4*)(VL + dst) = *(const uint4*)(gl + base + voff + c * 8);
        }
        __syncthreads();

        float sA[4][4];
        #pragma unroll
        for (int nt = 0; nt < 4; nt++)
            #pragma unroll
            for (int j = 0; j < 4; j++) sA[nt][j] = 0.f;

        #pragma unroll
        for (int ks = 0; ks < 16; ks++) {
            uint32_t ah[4], al[4];
            uint32_t qoff = (uint32_t)(qrow * QSTR + ks * 16 + qcol8) * 2;
            LDSM_X4(ah[0], ah[1], ah[2], ah[3], qh_b + qoff);
            LDSM_X4(al[0], al[1], al[2], al[3], ql_b + qoff);
            #pragma unroll
            for (int ntp = 0; ntp < 2; ntp++) {
                uint32_t bh[4], bl[4];
                uint32_t kofs = (uint32_t)((16 * ntp + krow) * QSTR + ks * 16 + kcol8) * 2;
                LDSM_X4(bh[0], bh[1], bh[2], bh[3], kh_b + kofs);
                LDSM_X4(bl[0], bl[1], bl[2], bl[3], kl_b + kofs);
                MMA_BF16(sA[2 * ntp],     ah, bh);
                MMA_BF16(sA[2 * ntp],     ah, bl);
                MMA_BF16(sA[2 * ntp],     al, bh);
                MMA_BF16(sA[2 * ntp + 1], ah, bh + 2);
                MMA_BF16(sA[2 * ntp + 1], ah, bl + 2);
                MMA_BF16(sA[2 * ntp + 1], al, bh + 2);
            }
        }

        // fixed-max softmax: P = exp(S - 6)
        #pragma unroll
        for (int nt = 0; nt < 4; nt++) {
            sA[nt][0] = ex2f(fmaf(sA[nt][0], LOG2E_, -MSHIFT_));
            sA[nt][1] = ex2f(fmaf(sA[nt][1], LOG2E_, -MSHIFT_));
            sA[nt][2] = ex2f(fmaf(sA[nt][2], LOG2E_, -MSHIFT_));
            sA[nt][3] = ex2f(fmaf(sA[nt][3], LOG2E_, -MSHIFT_));
            l_lo += sA[nt][0] + sA[nt][1];
            l_hi += sA[nt][2] + sA[nt][3];
        }

        uint32_t aPh[2][4], aPl[2][4];
        #pragma unroll
        for (int ksp = 0; ksp < 2; ksp++) {
            #pragma unroll
            for (int q = 0; q < 4; q++) {
                int nt = 2 * ksp + (q >> 1);
                int j0 = (q & 1) * 2;
                float p0 = sA[nt][j0], p1 = sA[nt][j0 + 1];
                float h0 = bf_round(p0), h1 = bf_round(p1);
                aPh[ksp][q] = pack_bf16(h0, h1);
                aPl[ksp][q] = pack_bf16(p0 - h0, p1 - h1);
            }
        }

        #pragma unroll
        for (int ksp = 0; ksp < 2; ksp++) {
            #pragma unroll
            for (int nt = 0; nt < 32; nt++) {
                uint32_t vofs = (uint32_t)((16 * ksp + vrow) * QSTR + nt * 8) * 2;
                uint32_t bv[2], bw[2];
                LDSM_X2T(bv[0], bv[1], vh_b + vofs);
                LDSM_X2T(bw[0], bw[1], vl_b + vofs);
                MMA_BF16(o[nt], aPh[ksp], bv);
                MMA_BF16(o[nt], aPh[ksp], bw);
                MMA_BF16(o[nt], aPl[ksp], bv);
            }
        }
    }

    l_lo += __shfl_xor_sync(~0u, l_lo, 1);
    l_lo += __shfl_xor_sync(~0u, l_lo, 2);
    l_hi += __shfl_xor_sync(~0u, l_hi, 1);
    l_hi += __shfl_xor_sync(~0u, l_hi, 2);

    float inv_lo = 1.0f / l_lo;
    float inv_hi = 1.0f / l_hi;
    const int row_lo = q0 + 16 * w + (l >> 2);
    const int col0 = h * HD_ + 2 * (l & 3);
    #pragma unroll
    for (int nt = 0; nt < 32; nt++) {
        float v0 = o[nt][0] * inv_lo, v1 = o[nt][1] * inv_lo;
        float v2 = o[nt][2] * inv_hi, v3 = o[nt][3] * inv_hi;
        float h0 = bf_round(v0), h1 = bf_round(v1);
        float h2 = bf_round(v2), h3 = bf_round(v3);
        size_t i0 = (size_t)(b * S_ + row_lo)     * (NH_ * HD_) + col0 + nt * 8;
        size_t i1 = (size_t)(b * S_ + row_lo + 8) * (NH_ * HD_) + col0 + nt * 8;
        *(uint32_t*)(aoh + i0) = pack_bf16(h0, h1);
        *(uint32_t*)(aol + i0) = pack_bf16(v0 - h0, v1 - h1);
        *(uint32_t*)(aoh + i1) = pack_bf16(h2, h3);
        *(uint32_t*)(aol + i1) = pack_bf16(v2 - h2, v3 - h3);
    }
}

// ---------------------------------------------------------------------------
// Launch
// ---------------------------------------------------------------------------
extern "C" void kernel_launch(void* const* d_in, const int* in_sizes, int n_in,
                              void* d_out, int out_size)
{
    const float* hidden = (const float*)d_in[0];
    const float* cosb   = (const float*)d_in[1];
    const float* sinb   = (const float*)d_in[2];
    const float* w_qkv  = (const float*)d_in[3];
    const float* w_o    = (const float*)d_in[4];
    const float* q_w    = (const float*)d_in[5];
    const float* k_w    = (const float*)d_in[6];
    float* out = (float*)d_out;

    float* qkv; cudaGetSymbolAddress((void**)&qkv, g_qkv);
    __nv_bfloat16 *gh, *gl, *hidh, *hidl, *wqh, *wql, *woh, *wol, *aoh, *aol;
    cudaGetSymbolAddress((void**)&gh,   g_h);
    cudaGetSymbolAddress((void**)&gl,   g_l);
    cudaGetSymbolAddress((void**)&hidh, g_hidh);
    cudaGetSymbolAddress((void**)&hidl, g_hidl);
    cudaGetSymbolAddress((void**)&wqh,  g_wqh);
    cudaGetSymbolAddress((void**)&wql,  g_wql);
    cudaGetSymbolAddress((void**)&woh,  g_woh);
    cudaGetSymbolAddress((void**)&wol,  g_wol);
    cudaGetSymbolAddress((void**)&aoh,  g_aoh);
    cudaGetSymbolAddress((void**)&aol,  g_aol);

    cudaFuncSetAttribute(fattn_kernel, cudaFuncAttributeMaxDynamicSharedMemorySize,
                         FATTN_SMEM);
    cudaFuncSetAttribute(tc_gemm_kernel, cudaFuncAttributeMaxDynamicSharedMemorySize,
                         TCG_SMEM);

    // 0) Split hidden; transpose+split weights to [N][K]
    {
        int n4 = M1_ * HID_ / 4;
        split_f32_kernel<<<(n4 + 255) / 256, 256>>>(hidden, hidh, hidl, n4);
        dim3 gq(F_ / 32, HID_ / 32);
        transpose_split_kernel<<<gq, 256>>>(w_qkv, wqh, wql, HID_, F_);
        dim3 go(HID_ / 32, (NH_ * HD_) / 32);
        transpose_split_kernel<<<go, 256>>>(w_o, woh, wol, NH_ * HD_, HID_);
    }

    // 1) QKV projection: [4096,2048] @ [2048,8192]
    {
        dim3 grid(F_ / 256, M1_ / 128);
        tc_gemm_kernel<<<grid, 256, TCG_SMEM>>>(hidh, hidl, wqh, wql,
                                                qkv, M1_, F_, HID_);
    }

    // 2) RMSNorm + RoPE + bf16 hi/lo split for attention
    split_kernel<<<M1_ * 32, 256>>>(qkv, cosb, sinb, q_w, k_w, gh, gl);

    // 3) Flash attention (tensor cores) -> writes bf16 hi/lo O-proj input
    fattn_kernel<<<B_ * NH_ * (S_ / 128), 256, FATTN_SMEM>>>(gh, gl, aoh, aol);

    // 4) Output projection: [4096,4096] @ [4096,2048]
    {
        dim3 grid(HID_ / 256, M1_ / 128);
        tc_gemm_kernel<<<grid, 256, TCG_SMEM>>>(aoh, aol, woh, wol,
                                                out, M1_, HID_, NH_ * HD_);
    }
}